// round 8
// baseline (speedup 1.0000x reference)
#include <cuda_runtime.h>
#include <math.h>
#include <stdint.h>

// ---------------- problem constants ----------------
#define B_    32
#define N_    3136
#define C_    512
#define H_    56
#define NH_   8
#define HD_   64
#define ANUM_ 49
#define SCALE_F 0.125f
#define M_    (B_ * N_)          // 100352

// ---------------- scratch ----------------
__device__ float g_qkv[(size_t)M_ * 1536];      // [b,n,{q|k|v},c]
__device__ float g_agent[B_ * ANUM_ * C_];
__device__ float g_num[B_ * NH_ * ANUM_ * HD_];
__device__ float g_den[B_ * NH_ * ANUM_];
__device__ float g_out[(size_t)M_ * C_];        // tf32(x) scratch, then attn+dwc out
__device__ float g_w[1536 * 512 + 512 * 512];   // tf32 qkv_w | proj_w

// ---------------- tf32 helpers ----------------
__device__ __forceinline__ float f2tf(float x) {
    uint32_t u;
    asm("cvt.rna.tf32.f32 %0, %1;" : "=r"(u) : "f"(x));
    return __uint_as_float(u);
}

__device__ __forceinline__ void mma_tf32(float* c, const uint32_t* a, const uint32_t* b) {
    asm volatile(
        "mma.sync.aligned.m16n8k8.row.col.f32.tf32.tf32.f32 "
        "{%0,%1,%2,%3}, {%4,%5,%6,%7}, {%8,%9}, {%0,%1,%2,%3};\n"
        : "+f"(c[0]), "+f"(c[1]), "+f"(c[2]), "+f"(c[3])
        : "r"(a[0]), "r"(a[1]), "r"(a[2]), "r"(a[3]), "r"(b[0]), "r"(b[1]));
}

__device__ __forceinline__ uint32_t smem_u32(const void* p) {
    uint32_t a;
    asm("{ .reg .u64 t; cvta.to.shared.u64 t, %1; cvt.u32.u64 %0, t; }" : "=r"(a) : "l"(p));
    return a;
}

__device__ __forceinline__ void cp16(uint32_t dst, const void* src) {
    asm volatile("cp.async.cg.shared.global [%0], [%1], 16;" :: "r"(dst), "l"(src));
}

// ---------------- tf32 pre-convert ----------------
__global__ void cvt_tf32(const float* __restrict__ src, float* __restrict__ dst, int n4)
{
    const int i = blockIdx.x * 256 + threadIdx.x;
    if (i < n4) {
        float4 v = ((const float4*)src)[i];
        v.x = f2tf(v.x); v.y = f2tf(v.y); v.z = f2tf(v.z); v.w = f2tf(v.w);
        ((float4*)dst)[i] = v;
    }
}

// ---------------- pipelined tensor-core GEMM, 4 warps x 64x64 warp tiles ---------
// C[M,N] = A[M,K] * B[N,K]^T (+bias). 128x128 CTA tile, BK=16, 3-stage cp.async
// ring, 128 threads. Warp tile 64x64 = 4x8 m16n8k8 frags -> halves smem crossbar
// traffic per output vs the 8-warp 64x32 version (crossbar was the binder at
// tensor=51%).
#define ASTR 20
#define G4_SMEM ((6 * 128 * ASTR + 128) * 4)   // 3x(A+B) stages + bias

__global__ void __launch_bounds__(128)
gemm_mma4(const float* __restrict__ A, const float* __restrict__ Bw,
          float* __restrict__ C, const float* __restrict__ bias,
          int K, int lda, int ldb, int ldc)
{
    extern __shared__ float smem[];
    float (*As)[128][ASTR] = (float(*)[128][ASTR])smem;
    float (*Bs)[128][ASTR] = (float(*)[128][ASTR])(smem + 3 * 128 * ASTR);
    float* bsh = smem + 6 * 128 * ASTR;

    const uint32_t aBase = smem_u32(smem);
    const uint32_t bBase = aBase + 3 * 128 * ASTR * 4;

    const int tid = threadIdx.x;
    const int wid = tid >> 5, lane = tid & 31;
    const int g = lane >> 2, t = lane & 3;
    const int wm = (wid >> 1) * 64;          // warp M offset (0 / 64)
    const int wn = (wid & 1) * 64;           // warp N offset (0 / 64)
    const long bm0 = (long)blockIdx.y * 128;
    const long bn0 = (long)blockIdx.x * 128;
    const int lr = tid >> 2;                 // loader row 0..31 (+32r)
    const int lj = tid & 3;                  // 16B chunk 0..3

    bsh[tid] = bias ? bias[bn0 + tid] : 0.f;

    const float* Ag = A + (bm0 + lr) * (long)lda + lj * 4;
    const float* Bg = Bw + (bn0 + lr) * (long)ldb + lj * 4;
    const long a32 = 32l * lda, b32 = 32l * ldb;
    const uint32_t soff = (uint32_t)(lr * ASTR + lj * 4) * 4;
    const uint32_t srow32 = 32u * ASTR * 4;

    auto load_stage = [&](int s) {
        const int buf = s % 3;
        const float* Ap = Ag + s * 16;
        const float* Bp = Bg + s * 16;
        const uint32_t bofs = (uint32_t)(buf * 128 * ASTR * 4) + soff;
#pragma unroll
        for (int r = 0; r < 4; ++r) {
            cp16(aBase + bofs + r * srow32, Ap + r * a32);
            cp16(bBase + bofs + r * srow32, Bp + r * b32);
        }
        asm volatile("cp.async.commit_group;" ::: "memory");
    };

    float acc[4][8][4];
#pragma unroll
    for (int i = 0; i < 4; ++i)
#pragma unroll
        for (int j = 0; j < 8; ++j)
#pragma unroll
            for (int q = 0; q < 4; ++q) acc[i][j][q] = 0.f;

    const int nkt = K / 16;
    load_stage(0);
    load_stage(1);

    for (int kt = 0; kt < nkt; ++kt) {
        asm volatile("cp.async.wait_group 1;" ::: "memory");
        __syncthreads();
        const int cur = kt % 3;

#pragma unroll
        for (int ks = 0; ks < 16; ks += 8) {
            uint32_t af[4][4], bf[8][2];
#pragma unroll
            for (int mf = 0; mf < 4; ++mf) {
                const int row = wm + mf * 16 + g;
                af[mf][0] = __float_as_uint(As[cur][row][ks + t]);
                af[mf][1] = __float_as_uint(As[cur][row + 8][ks + t]);
                af[mf][2] = __float_as_uint(As[cur][row][ks + t + 4]);
                af[mf][3] = __float_as_uint(As[cur][row + 8][ks + t + 4]);
            }
#pragma unroll
            for (int nf = 0; nf < 8; ++nf) {
                const int col = wn + nf * 8 + g;
                bf[nf][0] = __float_as_uint(Bs[cur][col][ks + t]);
                bf[nf][1] = __float_as_uint(Bs[cur][col][ks + t + 4]);
            }
#pragma unroll
            for (int mf = 0; mf < 4; ++mf)
#pragma unroll
                for (int nf = 0; nf < 8; ++nf)
                    mma_tf32(acc[mf][nf], af[mf], bf[nf]);
        }

        if (kt + 2 < nkt) load_stage(kt + 2);
        else asm volatile("cp.async.commit_group;" ::: "memory");
    }

    // epilogue
#pragma unroll
    for (int mf = 0; mf < 4; ++mf) {
        const long row = bm0 + wm + mf * 16 + g;
#pragma unroll
        for (int nf = 0; nf < 8; ++nf) {
            const int col = wn + nf * 8 + 2 * t;
            float2 v0, v1;
            v0.x = acc[mf][nf][0] + bsh[col];
            v0.y = acc[mf][nf][1] + bsh[col + 1];
            v1.x = acc[mf][nf][2] + bsh[col];
            v1.y = acc[mf][nf][3] + bsh[col + 1];
            *(float2*)(C + row * (long)ldc + bn0 + col) = v0;
            *(float2*)(C + (row + 8) * (long)ldc + bn0 + col) = v1;
        }
    }
}

// ---------------- agent pooling ----------------
__global__ void pool_q()
{
    const int bp = blockIdx.x;
    const int b = bp / ANUM_, p = bp % ANUM_;
    const int ph = p / 7, pw = p % 7;
    const int c = threadIdx.x;
    float s = 0.f;
#pragma unroll
    for (int iy = 0; iy < 8; ++iy)
#pragma unroll
        for (int ix = 0; ix < 8; ++ix) {
            const int n = (ph * 8 + iy) * H_ + pw * 8 + ix;
            s += g_qkv[((size_t)(b * N_ + n)) * 1536 + c];
        }
    g_agent[((size_t)b * ANUM_ + p) * C_ + c] = s * 0.015625f;
}

__global__ void zero_acc()
{
    const int i = blockIdx.x * 256 + threadIdx.x;
    if (i < B_ * NH_ * ANUM_ * HD_) g_num[i] = 0.f;
    if (i < B_ * NH_ * ANUM_)       g_den[i] = 0.f;
}

// ---------------- agent attention ----------------
__global__ void __launch_bounds__(256)
agent_kv()
{
    const int bh = blockIdx.x;
    const int part = blockIdx.y;
    const int b = bh >> 3, h = bh & 7;

    __shared__ float ag[ANUM_][64];
    __shared__ float Ks[32][68];
    __shared__ float Vs[32][68];
    __shared__ float Ws[ANUM_][33];

    const int tid = threadIdx.x;
    for (int i = tid; i < ANUM_ * 16; i += 256) {
        const int a = i >> 4, c4 = (i & 15) << 2;
        *(float4*)&ag[a][c4] =
            *(const float4*)&g_agent[((size_t)(b * ANUM_ + a)) * C_ + h * HD_ + c4];
    }

    const int cq = tid & 15;
    const int a0 = tid >> 4;
    const int nA = (a0 == 0) ? 4 : 3;
    float acc[4][4];
#pragma unroll
    for (int k = 0; k < 4; ++k)
#pragma unroll
        for (int j = 0; j < 4; ++j) acc[k][j] = 0.f;
    float den = 0.f;

    __syncthreads();

    const int n0 = part * 448;
    for (int t = 0; t < 14; ++t) {
        const int nb = n0 + t * 32;
        for (int i = tid; i < 32 * 16; i += 256) {
            const int r = i >> 4, c4 = (i & 15) << 2;
            const size_t base = ((size_t)(b * N_ + nb + r)) * 1536 + h * HD_ + c4;
            *(float4*)&Ks[r][c4] = *(const float4*)&g_qkv[base + 512];
            *(float4*)&Vs[r][c4] = *(const float4*)&g_qkv[base + 1024];
        }
        __syncthreads();

        // phase 1: K-register-hoisted; agents inner (ag reads are broadcasts)
        {
            const int nt = tid & 31;
            const int arr = tid >> 5;    // 0..7; agents a = arr + 8j
            float s[7] = {0.f, 0.f, 0.f, 0.f, 0.f, 0.f, 0.f};
#pragma unroll
            for (int c4 = 0; c4 < 64; c4 += 4) {
                const float4 k4 = *(const float4*)&Ks[nt][c4];
#pragma unroll
                for (int j = 0; j < 7; ++j) {
                    const int a = arr + 8 * j;
                    if (a < ANUM_) {
                        const float4 a4 = *(const float4*)&ag[a][c4];
                        s[j] += a4.x * k4.x + a4.y * k4.y + a4.z * k4.z + a4.w * k4.w;
                    }
                }
            }
#pragma unroll
            for (int j = 0; j < 7; ++j) {
                const int a = arr + 8 * j;
                if (a < ANUM_) Ws[a][nt] = expf(s[j] * SCALE_F);
            }
        }
        __syncthreads();

        if (tid < ANUM_) {
#pragma unroll
            for (int nt = 0; nt < 32; ++nt) den += Ws[tid][nt];
        }

        // phase 2
#pragma unroll
        for (int nt = 0; nt < 32; ++nt) {
            const float4 v4 = *(const float4*)&Vs[nt][cq * 4];
#pragma unroll
            for (int k = 0; k < 4; ++k) {
                if (k < 3 || a0 == 0) {
                    const float w = Ws[a0 + 16 * k][nt];
                    acc[k][0] += w * v4.x; acc[k][1] += w * v4.y;
                    acc[k][2] += w * v4.z; acc[k][3] += w * v4.w;
                }
            }
        }
        __syncthreads();
    }

    for (int k = 0; k < nA; ++k) {
        const int a = a0 + 16 * k;
        float* p = &g_num[(((size_t)bh * ANUM_) + a) * HD_ + cq * 4];
        atomicAdd(p + 0, acc[k][0]); atomicAdd(p + 1, acc[k][1]);
        atomicAdd(p + 2, acc[k][2]); atomicAdd(p + 3, acc[k][3]);
    }
    if (tid < ANUM_) atomicAdd(&g_den[bh * ANUM_ + tid], den);
}

// ---------------- q attention + fused depthwise conv (+ fused agent_v norm) -----
__global__ void __launch_bounds__(128)
q_attn_dwc(const float* __restrict__ dwcw, const float* __restrict__ dwcb)
{
    const int bh = blockIdx.x;
    const int b = bh >> 3, h = bh & 7;
    __shared__ float ag[ANUM_][64];
    __shared__ float av[ANUM_][64];
    __shared__ float ws[64][9];
    __shared__ float wb[64];
    const int tid = threadIdx.x;
    for (int i = tid; i < ANUM_ * 16; i += 128) {
        const int a = i >> 4, c4 = (i & 15) << 2;
        *(float4*)&ag[a][c4] = *(const float4*)&g_agent[((size_t)(b * ANUM_ + a)) * C_ + h * HD_ + c4];
        const float inv = 1.f / g_den[bh * ANUM_ + a];
        float4 n4 = *(const float4*)&g_num[(((size_t)bh * ANUM_) + a) * HD_ + c4];
        n4.x *= inv; n4.y *= inv; n4.z *= inv; n4.w *= inv;
        *(float4*)&av[a][c4] = n4;
    }
    for (int i = tid; i < 64 * 9; i += 128) ws[i / 9][i % 9] = dwcw[(h * 64 + i / 9) * 9 + i % 9];
    if (tid < 64) wb[tid] = dwcb[h * 64 + tid];
    __syncthreads();

    const int n = blockIdx.y * 128 + tid;
    if (n >= N_) return;

    float4 q[16];
    const size_t qb = ((size_t)(b * N_ + n)) * 1536 + h * HD_;
#pragma unroll
    for (int i = 0; i < 16; ++i) q[i] = *(const float4*)&g_qkv[qb + 4 * i];

    float4 o[16];
#pragma unroll
    for (int i = 0; i < 16; ++i) { o[i].x = 0.f; o[i].y = 0.f; o[i].z = 0.f; o[i].w = 0.f; }
    float den = 0.f;

    for (int a = 0; a < ANUM_; ++a) {
        float s = 0.f;
#pragma unroll
        for (int i = 0; i < 16; ++i) {
            const float4 k4 = *(const float4*)&ag[a][4 * i];
            s += q[i].x * k4.x + q[i].y * k4.y + q[i].z * k4.z + q[i].w * k4.w;
        }
        const float w = expf(s * SCALE_F);
        den += w;
#pragma unroll
        for (int i = 0; i < 16; ++i) {
            const float4 v4 = *(const float4*)&av[a][4 * i];
            o[i].x += w * v4.x; o[i].y += w * v4.y; o[i].z += w * v4.z; o[i].w += w * v4.w;
        }
    }

    const float inv = 1.f / den;
#pragma unroll
    for (int i = 0; i < 16; ++i) {
        o[i].x = o[i].x * inv + wb[4 * i + 0];
        o[i].y = o[i].y * inv + wb[4 * i + 1];
        o[i].z = o[i].z * inv + wb[4 * i + 2];
        o[i].w = o[i].w * inv + wb[4 * i + 3];
    }

    // depthwise 3x3 on v (head slice), accumulated into o
    const int y = n / H_, x = n - y * H_;
#pragma unroll
    for (int ky = 0; ky < 3; ++ky) {
        const int yy = y + ky - 1;
        if (yy < 0 || yy >= H_) continue;
#pragma unroll
        for (int kx = 0; kx < 3; ++kx) {
            const int xx = x + kx - 1;
            if (xx < 0 || xx >= H_) continue;
            const int tap = ky * 3 + kx;
            const float* vp = &g_qkv[((size_t)(b * N_ + yy * H_ + xx)) * 1536 + 1024 + h * HD_];
#pragma unroll
            for (int i = 0; i < 16; ++i) {
                const float4 v4 = *(const float4*)(vp + 4 * i);
                o[i].x += v4.x * ws[4 * i + 0][tap];
                o[i].y += v4.y * ws[4 * i + 1][tap];
                o[i].z += v4.z * ws[4 * i + 2][tap];
                o[i].w += v4.w * ws[4 * i + 3][tap];
            }
        }
    }

    float* op = &g_out[((size_t)(b * N_ + n)) * C_ + h * HD_];
#pragma unroll
    for (int i = 0; i < 16; ++i) {
        float4 v;
        v.x = f2tf(o[i].x); v.y = f2tf(o[i].y); v.z = f2tf(o[i].z); v.w = f2tf(o[i].w);
        *(float4*)&op[4 * i] = v;
    }
}

// ---------------- launch ----------------
extern "C" void kernel_launch(void* const* d_in, const int* in_sizes, int n_in,
                              void* d_out, int out_size)
{
    const float* x      = (const float*)d_in[0];
    const float* qkv_w  = (const float*)d_in[1];
    const float* proj_w = (const float*)d_in[2];
    const float* proj_b = (const float*)d_in[3];
    const float* dwc_w  = (const float*)d_in[4];
    const float* dwc_b  = (const float*)d_in[5];
    float* out = (float*)d_out;

    float *p_qkv = nullptr, *p_out = nullptr, *p_w = nullptr;
    cudaGetSymbolAddress((void**)&p_qkv, g_qkv);
    cudaGetSymbolAddress((void**)&p_out, g_out);
    cudaGetSymbolAddress((void**)&p_w, g_w);

    cudaFuncSetAttribute(gemm_mma4, cudaFuncAttributeMaxDynamicSharedMemorySize, G4_SMEM);

    // 0. pre-convert inputs to tf32-rounded fp32 (x -> g_out scratch; weights -> g_w)
    cvt_tf32<<<(M_ * C_ / 4 + 255) / 256, 256>>>(x, p_out, M_ * C_ / 4);
    cvt_tf32<<<(1536 * 512 / 4 + 255) / 256, 256>>>(qkv_w, p_w, 1536 * 512 / 4);
    cvt_tf32<<<(512 * 512 / 4 + 255) / 256, 256>>>(proj_w, p_w + 1536 * 512, 512 * 512 / 4);

    // 1. QKV projection: [100352,512] @ [1536,512]^T -> g_qkv
    gemm_mma4<<<dim3(1536 / 128, M_ / 128), 128, G4_SMEM>>>(p_out, p_w, p_qkv, nullptr, 512, 512, 512, 1536);
    // 2. zero agent-attn accumulators
    zero_acc<<<(B_ * NH_ * ANUM_ * HD_ + 255) / 256, 256>>>();
    // 3. agent pooling
    pool_q<<<B_ * ANUM_, C_>>>();
    // 4. agent attention
    agent_kv<<<dim3(B_ * NH_, 7), 256>>>();
    // 5. q attention + fused dwc + fused agent_v normalization -> g_out (tf32-rounded)
    q_attn_dwc<<<dim3(B_ * NH_, (N_ + 127) / 128), 128>>>(dwc_w, dwc_b);
    // 6. output projection (+bias) -> d_out
    gemm_mma4<<<dim3(512 / 128, M_ / 128), 128, G4_SMEM>>>(p_out, p_w + 1536 * 512, out, proj_b, 512, 512, 512, 512);
}

// round 9
// speedup vs baseline: 1.1841x; 1.1841x over previous
#include <cuda_runtime.h>
#include <math.h>
#include <stdint.h>

// ---------------- problem constants ----------------
#define B_    32
#define N_    3136
#define C_    512
#define H_    56
#define NH_   8
#define HD_   64
#define ANUM_ 49
#define SCALE_F 0.125f
#define M_    (B_ * N_)          // 100352

// ---------------- scratch ----------------
__device__ float g_qkv[(size_t)M_ * 1536];      // [b,n,{q|k|v},c]
__device__ float g_agent[B_ * ANUM_ * C_];
__device__ float g_num[B_ * NH_ * ANUM_ * HD_];
__device__ float g_den[B_ * NH_ * ANUM_];
__device__ float g_out[(size_t)M_ * C_];        // tf32(x) scratch, then attn+dwc out
__device__ float g_w[1536 * 512 + 512 * 512];   // tf32 qkv_w | proj_w

// ---------------- tf32 helpers ----------------
__device__ __forceinline__ float f2tf(float x) {
    uint32_t u;
    asm("cvt.rna.tf32.f32 %0, %1;" : "=r"(u) : "f"(x));
    return __uint_as_float(u);
}

__device__ __forceinline__ void mma_tf32(float* c, const uint32_t* a, const uint32_t* b) {
    asm volatile(
        "mma.sync.aligned.m16n8k8.row.col.f32.tf32.tf32.f32 "
        "{%0,%1,%2,%3}, {%4,%5,%6,%7}, {%8,%9}, {%0,%1,%2,%3};\n"
        : "+f"(c[0]), "+f"(c[1]), "+f"(c[2]), "+f"(c[3])
        : "r"(a[0]), "r"(a[1]), "r"(a[2]), "r"(a[3]), "r"(b[0]), "r"(b[1]));
}

__device__ __forceinline__ void ldsm4(uint32_t* r, uint32_t addr) {
    asm volatile("ldmatrix.sync.aligned.m8n8.x4.shared.b16 {%0,%1,%2,%3}, [%4];"
                 : "=r"(r[0]), "=r"(r[1]), "=r"(r[2]), "=r"(r[3]) : "r"(addr));
}

__device__ __forceinline__ void ldsm2(uint32_t* r, uint32_t addr) {
    asm volatile("ldmatrix.sync.aligned.m8n8.x2.shared.b16 {%0,%1}, [%2];"
                 : "=r"(r[0]), "=r"(r[1]) : "r"(addr));
}

__device__ __forceinline__ uint32_t smem_u32(const void* p) {
    uint32_t a;
    asm("{ .reg .u64 t; cvta.to.shared.u64 t, %1; cvt.u32.u64 %0, t; }" : "=r"(a) : "l"(p));
    return a;
}

__device__ __forceinline__ void cp16(uint32_t dst, const void* src) {
    asm volatile("cp.async.cg.shared.global [%0], [%1], 16;" :: "r"(dst), "l"(src));
}

// ---------------- tf32 pre-convert ----------------
__global__ void cvt_tf32(const float* __restrict__ src, float* __restrict__ dst, int n4)
{
    const int i = blockIdx.x * 256 + threadIdx.x;
    if (i < n4) {
        float4 v = ((const float4*)src)[i];
        v.x = f2tf(v.x); v.y = f2tf(v.y); v.z = f2tf(v.z); v.w = f2tf(v.w);
        ((float4*)dst)[i] = v;
    }
}

// ---------------- pipelined tensor-core GEMM (ldmatrix + BK=32) ------------------
// C[M,N] = A[M,K] * B[N,K]^T (+bias). 128x128 CTA tile, BK=32, 3-stage cp.async
// ring, 256 threads / 8 warps (2x4), warp tile 64x32 (4x4 m16n8k8 frags).
// Fragments loaded with ldmatrix (A: x4, B: x2) -> 3x fewer smem instructions.
// launch_bounds(256,2) keeps regs <=128 so 2 CTAs (16 warps) stay resident.
#define ASTR   36
#define GBK    32
#define GSTG   3
#define G5_SMEM ((GSTG * 2 * 128 * ASTR + 128) * 4)

__global__ void __launch_bounds__(256, 2)
gemm_mma5(const float* __restrict__ A, const float* __restrict__ Bw,
          float* __restrict__ C, const float* __restrict__ bias,
          int K, int lda, int ldb, int ldc)
{
    extern __shared__ float smem[];
    float* bsh = smem + GSTG * 2 * 128 * ASTR;

    const uint32_t aSmem = smem_u32(smem);
    const uint32_t bSmem = aSmem + GSTG * 128 * ASTR * 4;
    const uint32_t stageB = 128u * ASTR * 4u;     // bytes per stage per matrix

    const int tid = threadIdx.x;
    const int wid = tid >> 5, lane = tid & 31;
    const int g = lane >> 2, t = lane & 3;
    const int wm = (wid >> 2) * 64;
    const int wn = (wid & 3) * 32;
    const long bm0 = (long)blockIdx.y * 128;
    const long bn0 = (long)blockIdx.x * 128;

    // loaders: 128 rows x 8 chunks (16B) per matrix per stage; 4 per thread
    const int lr = tid >> 3;                 // 0..31
    const int lj = tid & 7;                  // 0..7

    if (tid < 128) bsh[tid] = bias ? bias[bn0 + tid] : 0.f;

    const float* Ag = A + (bm0 + lr) * (long)lda + lj * 4;
    const float* Bg = Bw + (bn0 + lr) * (long)ldb + lj * 4;
    const long a32 = 32l * lda, b32 = 32l * ldb;
    const uint32_t soff = (uint32_t)(lr * ASTR + lj * 4) * 4;
    const uint32_t srow32 = 32u * ASTR * 4u;

    auto load_stage = [&](int s) {
        const int buf = s % GSTG;
        const float* Ap = Ag + s * GBK;
        const float* Bp = Bg + s * GBK;
        const uint32_t bofs = (uint32_t)buf * stageB + soff;
#pragma unroll
        for (int r = 0; r < 4; ++r) {
            cp16(aSmem + bofs + r * srow32, Ap + r * a32);
            cp16(bSmem + bofs + r * srow32, Bp + r * b32);
        }
        asm volatile("cp.async.commit_group;" ::: "memory");
    };

    // ldmatrix per-thread base offsets (bytes), stage/frag/ks added later
    const int aTile = lane >> 3;             // 0..3
    const uint32_t aBaseT =
        (uint32_t)(((wm + ((aTile & 1) * 8) + (lane & 7)) * ASTR + (aTile >> 1) * 4) * 4);
    const int bl = lane & 15;
    const int bTile = bl >> 3;               // 0..1
    const uint32_t bBaseT =
        (uint32_t)(((wn + (lane & 7) + 0) * ASTR + bTile * 4) * 4);   // +nf*8 rows later

    float acc[4][4][4];
#pragma unroll
    for (int i = 0; i < 4; ++i)
#pragma unroll
        for (int j = 0; j < 4; ++j)
#pragma unroll
            for (int q = 0; q < 4; ++q) acc[i][j][q] = 0.f;

    const int nkt = K / GBK;
    load_stage(0);
    load_stage(1);

    for (int kt = 0; kt < nkt; ++kt) {
        asm volatile("cp.async.wait_group 1;" ::: "memory");
        __syncthreads();
        const uint32_t aCur = aSmem + (uint32_t)(kt % GSTG) * stageB + aBaseT;
        const uint32_t bCur = bSmem + (uint32_t)(kt % GSTG) * stageB + bBaseT;

#pragma unroll
        for (int ks = 0; ks < GBK; ks += 8) {
            uint32_t af[4][4], bf[4][2];
#pragma unroll
            for (int mf = 0; mf < 4; ++mf)
                ldsm4(af[mf], aCur + (uint32_t)(mf * 16 * ASTR + ks) * 4);
#pragma unroll
            for (int nf = 0; nf < 4; ++nf)
                ldsm2(bf[nf], bCur + (uint32_t)(nf * 8 * ASTR + ks) * 4);
#pragma unroll
            for (int mf = 0; mf < 4; ++mf)
#pragma unroll
                for (int nf = 0; nf < 4; ++nf)
                    mma_tf32(acc[mf][nf], af[mf], bf[nf]);
        }

        if (kt + 2 < nkt) load_stage(kt + 2);
        else asm volatile("cp.async.commit_group;" ::: "memory");
    }

    // epilogue
#pragma unroll
    for (int mf = 0; mf < 4; ++mf) {
        const long row = bm0 + wm + mf * 16 + g;
#pragma unroll
        for (int nf = 0; nf < 4; ++nf) {
            const int col = wn + nf * 8 + 2 * t;
            float2 v0, v1;
            v0.x = acc[mf][nf][0] + bsh[col];
            v0.y = acc[mf][nf][1] + bsh[col + 1];
            v1.x = acc[mf][nf][2] + bsh[col];
            v1.y = acc[mf][nf][3] + bsh[col + 1];
            *(float2*)(C + row * (long)ldc + bn0 + col) = v0;
            *(float2*)(C + (row + 8) * (long)ldc + bn0 + col) = v1;
        }
    }
}

// ---------------- agent pooling ----------------
__global__ void pool_q()
{
    const int bp = blockIdx.x;
    const int b = bp / ANUM_, p = bp % ANUM_;
    const int ph = p / 7, pw = p % 7;
    const int c = threadIdx.x;
    float s = 0.f;
#pragma unroll
    for (int iy = 0; iy < 8; ++iy)
#pragma unroll
        for (int ix = 0; ix < 8; ++ix) {
            const int n = (ph * 8 + iy) * H_ + pw * 8 + ix;
            s += g_qkv[((size_t)(b * N_ + n)) * 1536 + c];
        }
    g_agent[((size_t)b * ANUM_ + p) * C_ + c] = s * 0.015625f;
}

__global__ void zero_acc()
{
    const int i = blockIdx.x * 256 + threadIdx.x;
    if (i < B_ * NH_ * ANUM_ * HD_) g_num[i] = 0.f;
    if (i < B_ * NH_ * ANUM_)       g_den[i] = 0.f;
}

// ---------------- agent attention ----------------
__global__ void __launch_bounds__(256)
agent_kv()
{
    const int bh = blockIdx.x;
    const int part = blockIdx.y;
    const int b = bh >> 3, h = bh & 7;

    __shared__ float ag[ANUM_][64];
    __shared__ float Ks[32][68];
    __shared__ float Vs[32][68];
    __shared__ float Ws[ANUM_][33];

    const int tid = threadIdx.x;
    for (int i = tid; i < ANUM_ * 16; i += 256) {
        const int a = i >> 4, c4 = (i & 15) << 2;
        *(float4*)&ag[a][c4] =
            *(const float4*)&g_agent[((size_t)(b * ANUM_ + a)) * C_ + h * HD_ + c4];
    }

    const int cq = tid & 15;
    const int a0 = tid >> 4;
    const int nA = (a0 == 0) ? 4 : 3;
    float acc[4][4];
#pragma unroll
    for (int k = 0; k < 4; ++k)
#pragma unroll
        for (int j = 0; j < 4; ++j) acc[k][j] = 0.f;
    float den = 0.f;

    __syncthreads();

    const int n0 = part * 448;
    for (int t = 0; t < 14; ++t) {
        const int nb = n0 + t * 32;
        for (int i = tid; i < 32 * 16; i += 256) {
            const int r = i >> 4, c4 = (i & 15) << 2;
            const size_t base = ((size_t)(b * N_ + nb + r)) * 1536 + h * HD_ + c4;
            *(float4*)&Ks[r][c4] = *(const float4*)&g_qkv[base + 512];
            *(float4*)&Vs[r][c4] = *(const float4*)&g_qkv[base + 1024];
        }
        __syncthreads();

        // phase 1: K-register-hoisted; agents inner (ag reads are broadcasts)
        {
            const int nt = tid & 31;
            const int arr = tid >> 5;    // 0..7; agents a = arr + 8j
            float s[7] = {0.f, 0.f, 0.f, 0.f, 0.f, 0.f, 0.f};
#pragma unroll
            for (int c4 = 0; c4 < 64; c4 += 4) {
                const float4 k4 = *(const float4*)&Ks[nt][c4];
#pragma unroll
                for (int j = 0; j < 7; ++j) {
                    const int a = arr + 8 * j;
                    if (a < ANUM_) {
                        const float4 a4 = *(const float4*)&ag[a][c4];
                        s[j] += a4.x * k4.x + a4.y * k4.y + a4.z * k4.z + a4.w * k4.w;
                    }
                }
            }
#pragma unroll
            for (int j = 0; j < 7; ++j) {
                const int a = arr + 8 * j;
                if (a < ANUM_) Ws[a][nt] = expf(s[j] * SCALE_F);
            }
        }
        __syncthreads();

        if (tid < ANUM_) {
#pragma unroll
            for (int nt = 0; nt < 32; ++nt) den += Ws[tid][nt];
        }

        // phase 2
#pragma unroll
        for (int nt = 0; nt < 32; ++nt) {
            const float4 v4 = *(const float4*)&Vs[nt][cq * 4];
#pragma unroll
            for (int k = 0; k < 4; ++k) {
                if (k < 3 || a0 == 0) {
                    const float w = Ws[a0 + 16 * k][nt];
                    acc[k][0] += w * v4.x; acc[k][1] += w * v4.y;
                    acc[k][2] += w * v4.z; acc[k][3] += w * v4.w;
                }
            }
        }
        __syncthreads();
    }

    for (int k = 0; k < nA; ++k) {
        const int a = a0 + 16 * k;
        float* p = &g_num[(((size_t)bh * ANUM_) + a) * HD_ + cq * 4];
        atomicAdd(p + 0, acc[k][0]); atomicAdd(p + 1, acc[k][1]);
        atomicAdd(p + 2, acc[k][2]); atomicAdd(p + 3, acc[k][3]);
    }
    if (tid < ANUM_) atomicAdd(&g_den[bh * ANUM_ + tid], den);
}

// ---------------- q attention + fused depthwise conv (+ fused agent_v norm) -----
__global__ void __launch_bounds__(128)
q_attn_dwc(const float* __restrict__ dwcw, const float* __restrict__ dwcb)
{
    const int bh = blockIdx.x;
    const int b = bh >> 3, h = bh & 7;
    __shared__ float ag[ANUM_][64];
    __shared__ float av[ANUM_][64];
    __shared__ float ws[64][9];
    __shared__ float wb[64];
    const int tid = threadIdx.x;
    for (int i = tid; i < ANUM_ * 16; i += 128) {
        const int a = i >> 4, c4 = (i & 15) << 2;
        *(float4*)&ag[a][c4] = *(const float4*)&g_agent[((size_t)(b * ANUM_ + a)) * C_ + h * HD_ + c4];
        const float inv = 1.f / g_den[bh * ANUM_ + a];
        float4 n4 = *(const float4*)&g_num[(((size_t)bh * ANUM_) + a) * HD_ + c4];
        n4.x *= inv; n4.y *= inv; n4.z *= inv; n4.w *= inv;
        *(float4*)&av[a][c4] = n4;
    }
    for (int i = tid; i < 64 * 9; i += 128) ws[i / 9][i % 9] = dwcw[(h * 64 + i / 9) * 9 + i % 9];
    if (tid < 64) wb[tid] = dwcb[h * 64 + tid];
    __syncthreads();

    const int n = blockIdx.y * 128 + tid;
    if (n >= N_) return;

    float4 q[16];
    const size_t qb = ((size_t)(b * N_ + n)) * 1536 + h * HD_;
#pragma unroll
    for (int i = 0; i < 16; ++i) q[i] = *(const float4*)&g_qkv[qb + 4 * i];

    float4 o[16];
#pragma unroll
    for (int i = 0; i < 16; ++i) { o[i].x = 0.f; o[i].y = 0.f; o[i].z = 0.f; o[i].w = 0.f; }
    float den = 0.f;

    for (int a = 0; a < ANUM_; ++a) {
        float s = 0.f;
#pragma unroll
        for (int i = 0; i < 16; ++i) {
            const float4 k4 = *(const float4*)&ag[a][4 * i];
            s += q[i].x * k4.x + q[i].y * k4.y + q[i].z * k4.z + q[i].w * k4.w;
        }
        const float w = expf(s * SCALE_F);
        den += w;
#pragma unroll
        for (int i = 0; i < 16; ++i) {
            const float4 v4 = *(const float4*)&av[a][4 * i];
            o[i].x += w * v4.x; o[i].y += w * v4.y; o[i].z += w * v4.z; o[i].w += w * v4.w;
        }
    }

    const float inv = 1.f / den;
#pragma unroll
    for (int i = 0; i < 16; ++i) {
        o[i].x = o[i].x * inv + wb[4 * i + 0];
        o[i].y = o[i].y * inv + wb[4 * i + 1];
        o[i].z = o[i].z * inv + wb[4 * i + 2];
        o[i].w = o[i].w * inv + wb[4 * i + 3];
    }

    // depthwise 3x3 on v (head slice), accumulated into o
    const int y = n / H_, x = n - y * H_;
#pragma unroll
    for (int ky = 0; ky < 3; ++ky) {
        const int yy = y + ky - 1;
        if (yy < 0 || yy >= H_) continue;
#pragma unroll
        for (int kx = 0; kx < 3; ++kx) {
            const int xx = x + kx - 1;
            if (xx < 0 || xx >= H_) continue;
            const int tap = ky * 3 + kx;
            const float* vp = &g_qkv[((size_t)(b * N_ + yy * H_ + xx)) * 1536 + 1024 + h * HD_];
#pragma unroll
            for (int i = 0; i < 16; ++i) {
                const float4 v4 = *(const float4*)(vp + 4 * i);
                o[i].x += v4.x * ws[4 * i + 0][tap];
                o[i].y += v4.y * ws[4 * i + 1][tap];
                o[i].z += v4.z * ws[4 * i + 2][tap];
                o[i].w += v4.w * ws[4 * i + 3][tap];
            }
        }
    }

    float* op = &g_out[((size_t)(b * N_ + n)) * C_ + h * HD_];
#pragma unroll
    for (int i = 0; i < 16; ++i) {
        float4 v;
        v.x = f2tf(o[i].x); v.y = f2tf(o[i].y); v.z = f2tf(o[i].z); v.w = f2tf(o[i].w);
        *(float4*)&op[4 * i] = v;
    }
}

// ---------------- launch ----------------
extern "C" void kernel_launch(void* const* d_in, const int* in_sizes, int n_in,
                              void* d_out, int out_size)
{
    const float* x      = (const float*)d_in[0];
    const float* qkv_w  = (const float*)d_in[1];
    const float* proj_w = (const float*)d_in[2];
    const float* proj_b = (const float*)d_in[3];
    const float* dwc_w  = (const float*)d_in[4];
    const float* dwc_b  = (const float*)d_in[5];
    float* out = (float*)d_out;

    float *p_qkv = nullptr, *p_out = nullptr, *p_w = nullptr;
    cudaGetSymbolAddress((void**)&p_qkv, g_qkv);
    cudaGetSymbolAddress((void**)&p_out, g_out);
    cudaGetSymbolAddress((void**)&p_w, g_w);

    cudaFuncSetAttribute(gemm_mma5, cudaFuncAttributeMaxDynamicSharedMemorySize, G5_SMEM);

    // 0. pre-convert inputs to tf32-rounded fp32 (x -> g_out scratch; weights -> g_w)
    cvt_tf32<<<(M_ * C_ / 4 + 255) / 256, 256>>>(x, p_out, M_ * C_ / 4);
    cvt_tf32<<<(1536 * 512 / 4 + 255) / 256, 256>>>(qkv_w, p_w, 1536 * 512 / 4);
    cvt_tf32<<<(512 * 512 / 4 + 255) / 256, 256>>>(proj_w, p_w + 1536 * 512, 512 * 512 / 4);

    // 1. QKV projection: [100352,512] @ [1536,512]^T -> g_qkv
    gemm_mma5<<<dim3(1536 / 128, M_ / 128), 256, G5_SMEM>>>(p_out, p_w, p_qkv, nullptr, 512, 512, 512, 1536);
    // 2. zero agent-attn accumulators
    zero_acc<<<(B_ * NH_ * ANUM_ * HD_ + 255) / 256, 256>>>();
    // 3. agent pooling
    pool_q<<<B_ * ANUM_, C_>>>();
    // 4. agent attention
    agent_kv<<<dim3(B_ * NH_, 7), 256>>>();
    // 5. q attention + fused dwc + fused agent_v normalization -> g_out (tf32-rounded)
    q_attn_dwc<<<dim3(B_ * NH_, (N_ + 127) / 128), 128>>>(dwc_w, dwc_b);
    // 6. output projection (+bias) -> d_out
    gemm_mma5<<<dim3(512 / 128, M_ / 128), 256, G5_SMEM>>>(p_out, p_w + 1536 * 512, out, proj_b, 512, 512, 512, 512);
}

// round 10
// speedup vs baseline: 1.4109x; 1.1916x over previous
#include <cuda_runtime.h>
#include <cuda_fp16.h>
#include <math.h>
#include <stdint.h>

// ---------------- problem constants ----------------
#define B_    32
#define N_    3136
#define C_    512
#define H_    56
#define NH_   8
#define HD_   64
#define ANUM_ 49
#define SCALE_F 0.125f
#define M_    (B_ * N_)          // 100352

// ---------------- scratch ----------------
__device__ float  g_qkv[(size_t)M_ * 1536];       // [b,n,{q|k|v},c] fp32
__device__ float  g_agent[B_ * ANUM_ * C_];
__device__ float  g_num[B_ * NH_ * ANUM_ * HD_];
__device__ float  g_den[B_ * NH_ * ANUM_];
__device__ __half g_x16[(size_t)M_ * C_];         // fp16(x)
__device__ __half g_o16[(size_t)M_ * C_];         // fp16 attention+dwc out
__device__ __half g_w16[1536 * 512 + 512 * 512];  // fp16 qkv_w | proj_w

// ---------------- helpers ----------------
__device__ __forceinline__ void mma_f16(float* c, const uint32_t* a, const uint32_t* b) {
    asm volatile(
        "mma.sync.aligned.m16n8k16.row.col.f32.f16.f16.f32 "
        "{%0,%1,%2,%3}, {%4,%5,%6,%7}, {%8,%9}, {%0,%1,%2,%3};\n"
        : "+f"(c[0]), "+f"(c[1]), "+f"(c[2]), "+f"(c[3])
        : "r"(a[0]), "r"(a[1]), "r"(a[2]), "r"(a[3]), "r"(b[0]), "r"(b[1]));
}

__device__ __forceinline__ void ldsm4(uint32_t* r, uint32_t addr) {
    asm volatile("ldmatrix.sync.aligned.m8n8.x4.shared.b16 {%0,%1,%2,%3}, [%4];"
                 : "=r"(r[0]), "=r"(r[1]), "=r"(r[2]), "=r"(r[3]) : "r"(addr));
}

__device__ __forceinline__ void ldsm2(uint32_t* r, uint32_t addr) {
    asm volatile("ldmatrix.sync.aligned.m8n8.x2.shared.b16 {%0,%1}, [%2];"
                 : "=r"(r[0]), "=r"(r[1]) : "r"(addr));
}

__device__ __forceinline__ uint32_t smem_u32(const void* p) {
    uint32_t a;
    asm("{ .reg .u64 t; cvta.to.shared.u64 t, %1; cvt.u32.u64 %0, t; }" : "=r"(a) : "l"(p));
    return a;
}

__device__ __forceinline__ void cp16(uint32_t dst, const void* src) {
    asm volatile("cp.async.cg.shared.global [%0], [%1], 16;" :: "r"(dst), "l"(src));
}

// ---------------- fp32 -> fp16 pre-convert ----------------
__global__ void cvt_f16(const float* __restrict__ src, __half* __restrict__ dst, int n4)
{
    const int i = blockIdx.x * 256 + threadIdx.x;
    if (i < n4) {
        float4 v = ((const float4*)src)[i];
        __half2 h0 = __floats2half2_rn(v.x, v.y);
        __half2 h1 = __floats2half2_rn(v.z, v.w);
        uint2 u;
        u.x = *(uint32_t*)&h0;
        u.y = *(uint32_t*)&h1;
        ((uint2*)dst)[i] = u;
    }
}

// ---------------- pipelined fp16 tensor-core GEMM --------------------------------
// C[M,N] = A[M,K] * B[N,K]^T (+bias), A/B fp16, C fp32. 128x128 CTA tile, BK=32,
// 3-stage cp.async ring, 256 threads / 8 warps (2x4), warp tile 64x32 =
// 4x4 m16n8k16 frags. ldmatrix A:x4 B:x2; 80-byte row stride is conflict-free.
#define HSTRB  80u                       // smem row stride in bytes (32 halves + 8 pad)
#define GBK    32                        // K elements per stage
#define GSTG   3
#define HSTAGE (128u * HSTRB)            // bytes per stage per matrix (10240)
#define GH_SMEM (GSTG * 2 * 10240 + 512)

__global__ void __launch_bounds__(256, 2)
gemm_h(const __half* __restrict__ A, const __half* __restrict__ Bw,
       float* __restrict__ C, const float* __restrict__ bias,
       int K, int lda, int ldb, int ldc)
{
    extern __shared__ char smemc[];
    float* bsh = (float*)(smemc + GSTG * 2 * 10240);

    const uint32_t aSmem = smem_u32(smemc);
    const uint32_t bSmem = aSmem + GSTG * HSTAGE;

    const int tid = threadIdx.x;
    const int wid = tid >> 5, lane = tid & 31;
    const int g = lane >> 2, t = lane & 3;
    const int wm = (wid >> 2) * 64;
    const int wn = (wid & 3) * 32;
    const long bm0 = (long)blockIdx.y * 128;
    const long bn0 = (long)blockIdx.x * 128;

    // loaders: 128 rows x 64 bytes per matrix per stage; rows lr, lr+64
    const int lr = tid >> 2;                 // 0..63
    const int lj = tid & 3;                  // 16B chunk 0..3

    if (tid < 128) bsh[tid] = bias ? bias[bn0 + tid] : 0.f;

    const __half* Ag = A + (bm0 + lr) * (long)lda + lj * 8;
    const __half* Bg = Bw + (bn0 + lr) * (long)ldb + lj * 8;
    const long a64 = 64l * lda, b64 = 64l * ldb;
    const uint32_t soff = (uint32_t)lr * HSTRB + (uint32_t)lj * 16u;

    auto load_stage = [&](int s) {
        const int buf = s % GSTG;
        const __half* Ap = Ag + s * GBK;
        const __half* Bp = Bg + s * GBK;
        const uint32_t bofs = (uint32_t)buf * HSTAGE + soff;
        cp16(aSmem + bofs, Ap);
        cp16(aSmem + bofs + 64u * HSTRB, Ap + a64);
        cp16(bSmem + bofs, Bp);
        cp16(bSmem + bofs + 64u * HSTRB, Bp + b64);
        asm volatile("cp.async.commit_group;" ::: "memory");
    };

    // ldmatrix per-lane offsets
    const int aTile = lane >> 3;             // 0..3
    const uint32_t aLane =
        (uint32_t)(((aTile & 1) * 8 + (lane & 7)) * HSTRB + (aTile >> 1) * 16);
    const uint32_t bLane =
        (uint32_t)((lane & 7) * HSTRB + ((lane >> 3) & 1) * 16);

    float acc[4][4][4];
#pragma unroll
    for (int i = 0; i < 4; ++i)
#pragma unroll
        for (int j = 0; j < 4; ++j)
#pragma unroll
            for (int q = 0; q < 4; ++q) acc[i][j][q] = 0.f;

    const int nkt = K / GBK;
    load_stage(0);
    load_stage(1);

    for (int kt = 0; kt < nkt; ++kt) {
        asm volatile("cp.async.wait_group 1;" ::: "memory");
        __syncthreads();
        const uint32_t aCur = aSmem + (uint32_t)(kt % GSTG) * HSTAGE + aLane;
        const uint32_t bCur = bSmem + (uint32_t)(kt % GSTG) * HSTAGE + bLane;

#pragma unroll
        for (int ks = 0; ks < 2; ++ks) {          // two k16 steps (32 halves)
            uint32_t af[4][4], bf[4][2];
#pragma unroll
            for (int mf = 0; mf < 4; ++mf)
                ldsm4(af[mf], aCur + (uint32_t)(wm + mf * 16) * HSTRB + ks * 32u);
#pragma unroll
            for (int nf = 0; nf < 4; ++nf)
                ldsm2(bf[nf], bCur + (uint32_t)(wn + nf * 8) * HSTRB + ks * 32u);
#pragma unroll
            for (int mf = 0; mf < 4; ++mf)
#pragma unroll
                for (int nf = 0; nf < 4; ++nf)
                    mma_f16(acc[mf][nf], af[mf], bf[nf]);
        }

        if (kt + 2 < nkt) load_stage(kt + 2);
        else asm volatile("cp.async.commit_group;" ::: "memory");
    }

    // epilogue
#pragma unroll
    for (int mf = 0; mf < 4; ++mf) {
        const long row = bm0 + wm + mf * 16 + g;
#pragma unroll
        for (int nf = 0; nf < 4; ++nf) {
            const int col = wn + nf * 8 + 2 * t;
            float2 v0, v1;
            v0.x = acc[mf][nf][0] + bsh[col];
            v0.y = acc[mf][nf][1] + bsh[col + 1];
            v1.x = acc[mf][nf][2] + bsh[col];
            v1.y = acc[mf][nf][3] + bsh[col + 1];
            *(float2*)(C + row * (long)ldc + bn0 + col) = v0;
            *(float2*)(C + (row + 8) * (long)ldc + bn0 + col) = v1;
        }
    }
}

// ---------------- agent pooling ----------------
__global__ void pool_q()
{
    const int bp = blockIdx.x;
    const int b = bp / ANUM_, p = bp % ANUM_;
    const int ph = p / 7, pw = p % 7;
    const int c = threadIdx.x;
    float s = 0.f;
#pragma unroll
    for (int iy = 0; iy < 8; ++iy)
#pragma unroll
        for (int ix = 0; ix < 8; ++ix) {
            const int n = (ph * 8 + iy) * H_ + pw * 8 + ix;
            s += g_qkv[((size_t)(b * N_ + n)) * 1536 + c];
        }
    g_agent[((size_t)b * ANUM_ + p) * C_ + c] = s * 0.015625f;
}

__global__ void zero_acc()
{
    const int i = blockIdx.x * 256 + threadIdx.x;
    if (i < B_ * NH_ * ANUM_ * HD_) g_num[i] = 0.f;
    if (i < B_ * NH_ * ANUM_)       g_den[i] = 0.f;
}

// ---------------- agent attention ----------------
__global__ void __launch_bounds__(256)
agent_kv()
{
    const int bh = blockIdx.x;
    const int part = blockIdx.y;
    const int b = bh >> 3, h = bh & 7;

    __shared__ float ag[ANUM_][64];
    __shared__ float Ks[32][68];
    __shared__ float Vs[32][68];
    __shared__ float Ws[ANUM_][33];

    const int tid = threadIdx.x;
    for (int i = tid; i < ANUM_ * 16; i += 256) {
        const int a = i >> 4, c4 = (i & 15) << 2;
        *(float4*)&ag[a][c4] =
            *(const float4*)&g_agent[((size_t)(b * ANUM_ + a)) * C_ + h * HD_ + c4];
    }

    const int cq = tid & 15;
    const int a0 = tid >> 4;
    const int nA = (a0 == 0) ? 4 : 3;
    float acc[4][4];
#pragma unroll
    for (int k = 0; k < 4; ++k)
#pragma unroll
        for (int j = 0; j < 4; ++j) acc[k][j] = 0.f;
    float den = 0.f;

    __syncthreads();

    const int n0 = part * 448;
    for (int t = 0; t < 14; ++t) {
        const int nb = n0 + t * 32;
        for (int i = tid; i < 32 * 16; i += 256) {
            const int r = i >> 4, c4 = (i & 15) << 2;
            const size_t base = ((size_t)(b * N_ + nb + r)) * 1536 + h * HD_ + c4;
            *(float4*)&Ks[r][c4] = *(const float4*)&g_qkv[base + 512];
            *(float4*)&Vs[r][c4] = *(const float4*)&g_qkv[base + 1024];
        }
        __syncthreads();

        // phase 1: K-register-hoisted; agents inner (ag reads are broadcasts)
        {
            const int nt = tid & 31;
            const int arr = tid >> 5;    // 0..7; agents a = arr + 8j
            float s[7] = {0.f, 0.f, 0.f, 0.f, 0.f, 0.f, 0.f};
#pragma unroll
            for (int c4 = 0; c4 < 64; c4 += 4) {
                const float4 k4 = *(const float4*)&Ks[nt][c4];
#pragma unroll
                for (int j = 0; j < 7; ++j) {
                    const int a = arr + 8 * j;
                    if (a < ANUM_) {
                        const float4 a4 = *(const float4*)&ag[a][c4];
                        s[j] += a4.x * k4.x + a4.y * k4.y + a4.z * k4.z + a4.w * k4.w;
                    }
                }
            }
#pragma unroll
            for (int j = 0; j < 7; ++j) {
                const int a = arr + 8 * j;
                if (a < ANUM_) Ws[a][nt] = expf(s[j] * SCALE_F);
            }
        }
        __syncthreads();

        if (tid < ANUM_) {
#pragma unroll
            for (int nt = 0; nt < 32; ++nt) den += Ws[tid][nt];
        }

        // phase 2
#pragma unroll
        for (int nt = 0; nt < 32; ++nt) {
            const float4 v4 = *(const float4*)&Vs[nt][cq * 4];
#pragma unroll
            for (int k = 0; k < 4; ++k) {
                if (k < 3 || a0 == 0) {
                    const float w = Ws[a0 + 16 * k][nt];
                    acc[k][0] += w * v4.x; acc[k][1] += w * v4.y;
                    acc[k][2] += w * v4.z; acc[k][3] += w * v4.w;
                }
            }
        }
        __syncthreads();
    }

    for (int k = 0; k < nA; ++k) {
        const int a = a0 + 16 * k;
        float* p = &g_num[(((size_t)bh * ANUM_) + a) * HD_ + cq * 4];
        atomicAdd(p + 0, acc[k][0]); atomicAdd(p + 1, acc[k][1]);
        atomicAdd(p + 2, acc[k][2]); atomicAdd(p + 3, acc[k][3]);
    }
    if (tid < ANUM_) atomicAdd(&g_den[bh * ANUM_ + tid], den);
}

// ---------------- q attention + fused depthwise conv (+ fused agent_v norm) -----
// writes fp16 directly (proj GEMM input)
__global__ void __launch_bounds__(128)
q_attn_dwc(const float* __restrict__ dwcw, const float* __restrict__ dwcb)
{
    const int bh = blockIdx.x;
    const int b = bh >> 3, h = bh & 7;
    __shared__ float ag[ANUM_][64];
    __shared__ float av[ANUM_][64];
    __shared__ float ws[64][9];
    __shared__ float wb[64];
    const int tid = threadIdx.x;
    for (int i = tid; i < ANUM_ * 16; i += 128) {
        const int a = i >> 4, c4 = (i & 15) << 2;
        *(float4*)&ag[a][c4] = *(const float4*)&g_agent[((size_t)(b * ANUM_ + a)) * C_ + h * HD_ + c4];
        const float inv = 1.f / g_den[bh * ANUM_ + a];
        float4 n4 = *(const float4*)&g_num[(((size_t)bh * ANUM_) + a) * HD_ + c4];
        n4.x *= inv; n4.y *= inv; n4.z *= inv; n4.w *= inv;
        *(float4*)&av[a][c4] = n4;
    }
    for (int i = tid; i < 64 * 9; i += 128) ws[i / 9][i % 9] = dwcw[(h * 64 + i / 9) * 9 + i % 9];
    if (tid < 64) wb[tid] = dwcb[h * 64 + tid];
    __syncthreads();

    const int n = blockIdx.y * 128 + tid;
    if (n >= N_) return;

    float4 q[16];
    const size_t qb = ((size_t)(b * N_ + n)) * 1536 + h * HD_;
#pragma unroll
    for (int i = 0; i < 16; ++i) q[i] = *(const float4*)&g_qkv[qb + 4 * i];

    float4 o[16];
#pragma unroll
    for (int i = 0; i < 16; ++i) { o[i].x = 0.f; o[i].y = 0.f; o[i].z = 0.f; o[i].w = 0.f; }
    float den = 0.f;

    for (int a = 0; a < ANUM_; ++a) {
        float s = 0.f;
#pragma unroll
        for (int i = 0; i < 16; ++i) {
            const float4 k4 = *(const float4*)&ag[a][4 * i];
            s += q[i].x * k4.x + q[i].y * k4.y + q[i].z * k4.z + q[i].w * k4.w;
        }
        const float w = expf(s * SCALE_F);
        den += w;
#pragma unroll
        for (int i = 0; i < 16; ++i) {
            const float4 v4 = *(const float4*)&av[a][4 * i];
            o[i].x += w * v4.x; o[i].y += w * v4.y; o[i].z += w * v4.z; o[i].w += w * v4.w;
        }
    }

    const float inv = 1.f / den;
#pragma unroll
    for (int i = 0; i < 16; ++i) {
        o[i].x = o[i].x * inv + wb[4 * i + 0];
        o[i].y = o[i].y * inv + wb[4 * i + 1];
        o[i].z = o[i].z * inv + wb[4 * i + 2];
        o[i].w = o[i].w * inv + wb[4 * i + 3];
    }

    // depthwise 3x3 on v (head slice), accumulated into o
    const int y = n / H_, x = n - y * H_;
#pragma unroll
    for (int ky = 0; ky < 3; ++ky) {
        const int yy = y + ky - 1;
        if (yy < 0 || yy >= H_) continue;
#pragma unroll
        for (int kx = 0; kx < 3; ++kx) {
            const int xx = x + kx - 1;
            if (xx < 0 || xx >= H_) continue;
            const int tap = ky * 3 + kx;
            const float* vp = &g_qkv[((size_t)(b * N_ + yy * H_ + xx)) * 1536 + 1024 + h * HD_];
#pragma unroll
            for (int i = 0; i < 16; ++i) {
                const float4 v4 = *(const float4*)(vp + 4 * i);
                o[i].x += v4.x * ws[4 * i + 0][tap];
                o[i].y += v4.y * ws[4 * i + 1][tap];
                o[i].z += v4.z * ws[4 * i + 2][tap];
                o[i].w += v4.w * ws[4 * i + 3][tap];
            }
        }
    }

    __half* op = &g_o16[((size_t)(b * N_ + n)) * C_ + h * HD_];
#pragma unroll
    for (int i = 0; i < 16; ++i) {
        __half2 h0 = __floats2half2_rn(o[i].x, o[i].y);
        __half2 h1 = __floats2half2_rn(o[i].z, o[i].w);
        uint2 u;
        u.x = *(uint32_t*)&h0;
        u.y = *(uint32_t*)&h1;
        *(uint2*)(op + 4 * i) = u;
    }
}

// ---------------- launch ----------------
extern "C" void kernel_launch(void* const* d_in, const int* in_sizes, int n_in,
                              void* d_out, int out_size)
{
    const float* x      = (const float*)d_in[0];
    const float* qkv_w  = (const float*)d_in[1];
    const float* proj_w = (const float*)d_in[2];
    const float* proj_b = (const float*)d_in[3];
    const float* dwc_w  = (const float*)d_in[4];
    const float* dwc_b  = (const float*)d_in[5];
    float* out = (float*)d_out;

    float *p_qkv = nullptr;
    __half *p_x16 = nullptr, *p_o16 = nullptr, *p_w16 = nullptr;
    cudaGetSymbolAddress((void**)&p_qkv, g_qkv);
    cudaGetSymbolAddress((void**)&p_x16, g_x16);
    cudaGetSymbolAddress((void**)&p_o16, g_o16);
    cudaGetSymbolAddress((void**)&p_w16, g_w16);

    cudaFuncSetAttribute(gemm_h, cudaFuncAttributeMaxDynamicSharedMemorySize, GH_SMEM);

    // 0. pre-convert inputs to fp16
    cvt_f16<<<(M_ * C_ / 4 + 255) / 256, 256>>>(x, p_x16, M_ * C_ / 4);
    cvt_f16<<<(1536 * 512 / 4 + 255) / 256, 256>>>(qkv_w, p_w16, 1536 * 512 / 4);
    cvt_f16<<<(512 * 512 / 4 + 255) / 256, 256>>>(proj_w, p_w16 + 1536 * 512, 512 * 512 / 4);

    // 1. QKV projection: [100352,512] @ [1536,512]^T -> g_qkv (fp32)
    gemm_h<<<dim3(1536 / 128, M_ / 128), 256, GH_SMEM>>>(p_x16, p_w16, p_qkv, nullptr, 512, 512, 512, 1536);
    // 2. zero agent-attn accumulators
    zero_acc<<<(B_ * NH_ * ANUM_ * HD_ + 255) / 256, 256>>>();
    // 3. agent pooling
    pool_q<<<B_ * ANUM_, C_>>>();
    // 4. agent attention
    agent_kv<<<dim3(B_ * NH_, 7), 256>>>();
    // 5. q attention + fused dwc + fused agent_v normalization -> g_o16 (fp16)
    q_attn_dwc<<<dim3(B_ * NH_, (N_ + 127) / 128), 128>>>(dwc_w, dwc_b);
    // 6. output projection (+bias) -> d_out
    gemm_h<<<dim3(512 / 128, M_ / 128), 256, GH_SMEM>>>(p_o16, p_w16 + 1536 * 512, out, proj_b, 512, 512, 512, 512);
}

// round 12
// speedup vs baseline: 1.6044x; 1.1372x over previous
#include <cuda_runtime.h>
#include <cuda_fp16.h>
#include <math.h>
#include <stdint.h>

// ---------------- problem constants ----------------
#define B_    32
#define N_    3136
#define C_    512
#define H_    56
#define NH_   8
#define HD_   64
#define ANUM_ 49
#define SCALE_F 0.125f
#define M_    (B_ * N_)          // 100352

// ---------------- scratch ----------------
__device__ float  g_qkv[(size_t)M_ * 1536];       // [b,n,{q|k|v},c] fp32
__device__ __half g_qkv16[(size_t)M_ * 1536];     // fp16 copy (written by qkv GEMM)
__device__ float  g_agent[B_ * ANUM_ * C_];
__device__ float  g_num[B_ * NH_ * ANUM_ * HD_];
__device__ float  g_den[B_ * NH_ * ANUM_];
__device__ __half g_x16[(size_t)M_ * C_];         // fp16(x)
__device__ __half g_o16[(size_t)M_ * C_];         // fp16 attention+dwc out
__device__ __half g_w16[1536 * 512 + 512 * 512];  // fp16 qkv_w | proj_w

// ---------------- helpers ----------------
__device__ __forceinline__ void mma_f16(float* c, const uint32_t* a, const uint32_t* b) {
    asm volatile(
        "mma.sync.aligned.m16n8k16.row.col.f32.f16.f16.f32 "
        "{%0,%1,%2,%3}, {%4,%5,%6,%7}, {%8,%9}, {%0,%1,%2,%3};\n"
        : "+f"(c[0]), "+f"(c[1]), "+f"(c[2]), "+f"(c[3])
        : "r"(a[0]), "r"(a[1]), "r"(a[2]), "r"(a[3]), "r"(b[0]), "r"(b[1]));
}

__device__ __forceinline__ void ldsm4(uint32_t* r, uint32_t addr) {
    asm volatile("ldmatrix.sync.aligned.m8n8.x4.shared.b16 {%0,%1,%2,%3}, [%4];"
                 : "=r"(r[0]), "=r"(r[1]), "=r"(r[2]), "=r"(r[3]) : "r"(addr));
}

__device__ __forceinline__ void ldsm4t(uint32_t* r, uint32_t addr) {
    asm volatile("ldmatrix.sync.aligned.m8n8.x4.trans.shared.b16 {%0,%1,%2,%3}, [%4];"
                 : "=r"(r[0]), "=r"(r[1]), "=r"(r[2]), "=r"(r[3]) : "r"(addr));
}

__device__ __forceinline__ void ldsm2(uint32_t* r, uint32_t addr) {
    asm volatile("ldmatrix.sync.aligned.m8n8.x2.shared.b16 {%0,%1}, [%2];"
                 : "=r"(r[0]), "=r"(r[1]) : "r"(addr));
}

__device__ __forceinline__ uint32_t smem_u32(const void* p) {
    uint32_t a;
    asm("{ .reg .u64 t; cvta.to.shared.u64 t, %1; cvt.u32.u64 %0, t; }" : "=r"(a) : "l"(p));
    return a;
}

__device__ __forceinline__ void cp16(uint32_t dst, const void* src) {
    asm volatile("cp.async.cg.shared.global [%0], [%1], 16;" :: "r"(dst), "l"(src));
}

// ---------------- fp32 -> fp16 pre-convert ----------------
__global__ void cvt_f16(const float* __restrict__ src, __half* __restrict__ dst, int n4)
{
    const int i = blockIdx.x * 256 + threadIdx.x;
    if (i < n4) {
        float4 v = ((const float4*)src)[i];
        __half2 h0 = __floats2half2_rn(v.x, v.y);
        __half2 h1 = __floats2half2_rn(v.z, v.w);
        uint2 u;
        u.x = *(uint32_t*)&h0;
        u.y = *(uint32_t*)&h1;
        ((uint2*)dst)[i] = u;
    }
}

// ---------------- pipelined fp16 tensor-core GEMM --------------------------------
// C[M,N] = A[M,K] * B[N,K]^T (+bias), A/B fp16, C fp32 (+optional fp16 copy C16).
#define HSTRB  80u
#define GBK    32
#define GSTG   3
#define HSTAGE (128u * HSTRB)
#define GH_SMEM (GSTG * 2 * 10240 + 512)

__global__ void __launch_bounds__(256, 2)
gemm_h(const __half* __restrict__ A, const __half* __restrict__ Bw,
       float* __restrict__ C, __half* __restrict__ C16,
       const float* __restrict__ bias,
       int K, int lda, int ldb, int ldc)
{
    extern __shared__ char smemc[];
    float* bsh = (float*)(smemc + GSTG * 2 * 10240);

    const uint32_t aSmem = smem_u32(smemc);
    const uint32_t bSmem = aSmem + GSTG * HSTAGE;

    const int tid = threadIdx.x;
    const int wid = tid >> 5, lane = tid & 31;
    const int g = lane >> 2, t = lane & 3;
    const int wm = (wid >> 2) * 64;
    const int wn = (wid & 3) * 32;
    const long bm0 = (long)blockIdx.y * 128;
    const long bn0 = (long)blockIdx.x * 128;

    const int lr = tid >> 2;
    const int lj = tid & 3;

    if (tid < 128) bsh[tid] = bias ? bias[bn0 + tid] : 0.f;

    const __half* Ag = A + (bm0 + lr) * (long)lda + lj * 8;
    const __half* Bg = Bw + (bn0 + lr) * (long)ldb + lj * 8;
    const long a64 = 64l * lda, b64 = 64l * ldb;
    const uint32_t soff = (uint32_t)lr * HSTRB + (uint32_t)lj * 16u;

    auto load_stage = [&](int s) {
        const int buf = s % GSTG;
        const __half* Ap = Ag + s * GBK;
        const __half* Bp = Bg + s * GBK;
        const uint32_t bofs = (uint32_t)buf * HSTAGE + soff;
        cp16(aSmem + bofs, Ap);
        cp16(aSmem + bofs + 64u * HSTRB, Ap + a64);
        cp16(bSmem + bofs, Bp);
        cp16(bSmem + bofs + 64u * HSTRB, Bp + b64);
        asm volatile("cp.async.commit_group;" ::: "memory");
    };

    const int aTile = lane >> 3;
    const uint32_t aLane =
        (uint32_t)(((aTile & 1) * 8 + (lane & 7)) * HSTRB + (aTile >> 1) * 16);
    const uint32_t bLane =
        (uint32_t)((lane & 7) * HSTRB + ((lane >> 3) & 1) * 16);

    float acc[4][4][4];
#pragma unroll
    for (int i = 0; i < 4; ++i)
#pragma unroll
        for (int j = 0; j < 4; ++j)
#pragma unroll
            for (int q = 0; q < 4; ++q) acc[i][j][q] = 0.f;

    const int nkt = K / GBK;
    load_stage(0);
    load_stage(1);

    for (int kt = 0; kt < nkt; ++kt) {
        asm volatile("cp.async.wait_group 1;" ::: "memory");
        __syncthreads();
        const uint32_t aCur = aSmem + (uint32_t)(kt % GSTG) * HSTAGE + aLane;
        const uint32_t bCur = bSmem + (uint32_t)(kt % GSTG) * HSTAGE + bLane;

#pragma unroll
        for (int ks = 0; ks < 2; ++ks) {
            uint32_t af[4][4], bf[4][2];
#pragma unroll
            for (int mf = 0; mf < 4; ++mf)
                ldsm4(af[mf], aCur + (uint32_t)(wm + mf * 16) * HSTRB + ks * 32u);
#pragma unroll
            for (int nf = 0; nf < 4; ++nf)
                ldsm2(bf[nf], bCur + (uint32_t)(wn + nf * 8) * HSTRB + ks * 32u);
#pragma unroll
            for (int mf = 0; mf < 4; ++mf)
#pragma unroll
                for (int nf = 0; nf < 4; ++nf)
                    mma_f16(acc[mf][nf], af[mf], bf[nf]);
        }

        if (kt + 2 < nkt) load_stage(kt + 2);
        else asm volatile("cp.async.commit_group;" ::: "memory");
    }

    // epilogue (fp32 + optional fp16 copy)
#pragma unroll
    for (int mf = 0; mf < 4; ++mf) {
        const long row = bm0 + wm + mf * 16 + g;
#pragma unroll
        for (int nf = 0; nf < 4; ++nf) {
            const int col = wn + nf * 8 + 2 * t;
            float2 v0, v1;
            v0.x = acc[mf][nf][0] + bsh[col];
            v0.y = acc[mf][nf][1] + bsh[col + 1];
            v1.x = acc[mf][nf][2] + bsh[col];
            v1.y = acc[mf][nf][3] + bsh[col + 1];
            *(float2*)(C + row * (long)ldc + bn0 + col) = v0;
            *(float2*)(C + (row + 8) * (long)ldc + bn0 + col) = v1;
            if (C16) {
                __half2 h0 = __floats2half2_rn(v0.x, v0.y);
                __half2 h1 = __floats2half2_rn(v1.x, v1.y);
                *(uint32_t*)(C16 + row * (long)ldc + bn0 + col) = *(uint32_t*)&h0;
                *(uint32_t*)(C16 + (row + 8) * (long)ldc + bn0 + col) = *(uint32_t*)&h1;
            }
        }
    }
}

// ---------------- agent pooling ----------------
__global__ void pool_q()
{
    const int bp = blockIdx.x;
    const int b = bp / ANUM_, p = bp % ANUM_;
    const int ph = p / 7, pw = p % 7;
    const int c = threadIdx.x;
    float s = 0.f;
#pragma unroll
    for (int iy = 0; iy < 8; ++iy)
#pragma unroll
        for (int ix = 0; ix < 8; ++ix) {
            const int n = (ph * 8 + iy) * H_ + pw * 8 + ix;
            s += g_qkv[((size_t)(b * N_ + n)) * 1536 + c];
        }
    g_agent[((size_t)b * ANUM_ + p) * C_ + c] = s * 0.015625f;
}

__global__ void zero_acc()
{
    const int i = blockIdx.x * 256 + threadIdx.x;
    if (i < B_ * NH_ * ANUM_ * HD_) g_num[i] = 0.f;
    if (i < B_ * NH_ * ANUM_)       g_den[i] = 0.f;
}

// ---------------- agent attention via tensor cores ------------------------------
// Per (bh, part): stream 7 tiles of 64 tokens.
// phase1: logits[64 agents(pad) x 64 tok] = ag16 @ K16^T   (ag pre-scaled by SCALE)
// exp -> den (shfl + smem atomics) -> W fp16 in smem
// phase2: agent_v[64 x 64 dims] += W @ V  (V^T frags via ldmatrix.trans)
#define AKROW 144u                    // smem row stride bytes (72 halves)
#define AG_OFF  0u
#define W_OFF   9216u
#define KS_OFF  18432u                // + buf*9216
#define VS_OFF  36864u                // + buf*9216
#define DEN_OFF 55296u
#define AK_SMEM 55552

__global__ void __launch_bounds__(128)
agent_kv_mma()
{
    extern __shared__ char sm[];
    const uint32_t sb = smem_u32(sm);
    float* den_s = (float*)(sm + DEN_OFF);
    __half* ag16 = (__half*)(sm + AG_OFF);
    __half* Wsm  = (__half*)(sm + W_OFF);

    const int bh = blockIdx.x;
    const int part = blockIdx.y;
    const int b = bh >> 3, h = bh & 7;
    const int tid = threadIdx.x;
    const int wid = tid >> 5, lane = tid & 31;
    const int g = lane >> 2, t = lane & 3;
    const int wtok = wid * 16;           // phase1 token slice
    const int wdim = wid * 16;           // phase2 dim slice

    // load ag (fp32 -> fp16, pre-scaled by SCALE; pad agents 49..63 = 0)
    for (int i = tid; i < 64 * 64; i += 128) {
        const int a = i >> 6, d = i & 63;
        float v = 0.f;
        if (a < ANUM_)
            v = g_agent[((size_t)(b * ANUM_ + a)) * C_ + h * HD_ + d] * SCALE_F;
        ag16[a * 72 + d] = __float2half(v);
    }
    if (tid < 64) den_s[tid] = 0.f;
    __syncthreads();

    // ldmatrix lane patterns
    const int aTile = lane >> 3;
    const uint32_t aLane =
        (uint32_t)(((aTile & 1) * 8 + (lane & 7)) * AKROW + (aTile >> 1) * 16);
    const uint32_t bLane =
        (uint32_t)((lane & 7) * AKROW + ((lane >> 3) & 1) * 16);

    // hoist ag A-frags (constant across tiles)
    uint32_t agF[4][4][4];
#pragma unroll
    for (int mf = 0; mf < 4; ++mf)
#pragma unroll
        for (int ks = 0; ks < 4; ++ks)
            ldsm4(agF[mf][ks], sb + AG_OFF + aLane + (uint32_t)(mf * 16) * AKROW + ks * 32u);

    // tile loader (K,V fp16 -> smem, 64 tokens x 64 dims each; head slice!)
    const int ntok0 = part * 448;
    auto load_tile = [&](int tt) {
        const uint32_t buf = (uint32_t)(tt & 1) * 9216u;
#pragma unroll
        for (int it = 0; it < 4; ++it) {
            const int i = tid + it * 128;
            const int r = i >> 3, cch = i & 7;
            const __half* src =
                g_qkv16 + ((size_t)(b * N_ + ntok0 + tt * 64 + r)) * 1536 + 512 + h * HD_ + cch * 8;
            cp16(sb + KS_OFF + buf + (uint32_t)r * AKROW + cch * 16u, src);
            cp16(sb + VS_OFF + buf + (uint32_t)r * AKROW + cch * 16u, src + 512);
        }
        asm volatile("cp.async.commit_group;" ::: "memory");
    };

    float acc[4][2][4];
#pragma unroll
    for (int i = 0; i < 4; ++i)
#pragma unroll
        for (int j = 0; j < 2; ++j)
#pragma unroll
            for (int q = 0; q < 4; ++q) acc[i][j][q] = 0.f;

    load_tile(0);

    for (int tt = 0; tt < 7; ++tt) {
        asm volatile("cp.async.wait_group 0;" ::: "memory");
        __syncthreads();
        const uint32_t buf = (uint32_t)(tt & 1) * 9216u;

        // ---- phase 1: logits ----
        float c1[4][2][4];
#pragma unroll
        for (int i = 0; i < 4; ++i)
#pragma unroll
            for (int j = 0; j < 2; ++j)
#pragma unroll
                for (int q = 0; q < 4; ++q) c1[i][j][q] = 0.f;

#pragma unroll
        for (int ks = 0; ks < 4; ++ks) {
            uint32_t kF[2][2];
#pragma unroll
            for (int nf = 0; nf < 2; ++nf)
                ldsm2(kF[nf], sb + KS_OFF + buf + bLane +
                      (uint32_t)(wtok + nf * 8) * AKROW + ks * 32u);
#pragma unroll
            for (int mf = 0; mf < 4; ++mf)
#pragma unroll
                for (int nf = 0; nf < 2; ++nf)
                    mma_f16(c1[mf][nf], agF[mf][ks], kF[nf]);
        }

        // issue next tile loads (other buffer)
        if (tt + 1 < 7) load_tile(tt + 1);
        else asm volatile("cp.async.commit_group;" ::: "memory");

        // ---- exp, den, W store ----
#pragma unroll
        for (int mf = 0; mf < 4; ++mf) {
            float e[2][4];
#pragma unroll
            for (int nf = 0; nf < 2; ++nf)
#pragma unroll
                for (int q = 0; q < 4; ++q) e[nf][q] = expf(c1[mf][nf][q]);
            float d0 = e[0][0] + e[0][1] + e[1][0] + e[1][1];
            float d1 = e[0][2] + e[0][3] + e[1][2] + e[1][3];
            d0 += __shfl_xor_sync(0xffffffff, d0, 1);
            d0 += __shfl_xor_sync(0xffffffff, d0, 2);
            d1 += __shfl_xor_sync(0xffffffff, d1, 1);
            d1 += __shfl_xor_sync(0xffffffff, d1, 2);
            const int rowA = mf * 16 + g, rowB = rowA + 8;
            if (t == 0) {
                atomicAdd(&den_s[rowA], d0);
                atomicAdd(&den_s[rowB], d1);
            }
#pragma unroll
            for (int nf = 0; nf < 2; ++nf) {
                const int col = wtok + nf * 8 + 2 * t;
                __half2 h0 = __floats2half2_rn(e[nf][0], e[nf][1]);
                __half2 h1 = __floats2half2_rn(e[nf][2], e[nf][3]);
                *(uint32_t*)&Wsm[rowA * 72 + col] = *(uint32_t*)&h0;
                *(uint32_t*)&Wsm[rowB * 72 + col] = *(uint32_t*)&h1;
            }
        }
        __syncthreads();

        // ---- phase 2: agent_v += W @ V ----
#pragma unroll
        for (int ks = 0; ks < 4; ++ks) {
            uint32_t vF[4];
            ldsm4t(vF, sb + VS_OFF + buf +
                   (uint32_t)(ks * 16 + (lane & 15)) * AKROW +
                   (uint32_t)(wdim + (lane >> 4) * 8) * 2u);
#pragma unroll
            for (int mf = 0; mf < 4; ++mf) {
                uint32_t wF[4];
                ldsm4(wF, sb + W_OFF + aLane + (uint32_t)(mf * 16) * AKROW + ks * 32u);
                mma_f16(acc[mf][0], wF, vF);
                mma_f16(acc[mf][1], wF, vF + 2);
            }
        }
        __syncthreads();
    }

    // write out
    if (tid < ANUM_) atomicAdd(&g_den[bh * ANUM_ + tid], den_s[tid]);
#pragma unroll
    for (int mf = 0; mf < 4; ++mf) {
        const int rowA = mf * 16 + g, rowB = rowA + 8;
#pragma unroll
        for (int nf = 0; nf < 2; ++nf) {
            const int dim = wdim + nf * 8 + 2 * t;
            if (rowA < ANUM_) {
                float* p = &g_num[(((size_t)bh * ANUM_) + rowA) * HD_ + dim];
                atomicAdd(p, acc[mf][nf][0]);
                atomicAdd(p + 1, acc[mf][nf][1]);
            }
            if (rowB < ANUM_) {
                float* p = &g_num[(((size_t)bh * ANUM_) + rowB) * HD_ + dim];
                atomicAdd(p, acc[mf][nf][2]);
                atomicAdd(p + 1, acc[mf][nf][3]);
            }
        }
    }
}

// ---------------- q attention + fused depthwise conv (+ fused agent_v norm) -----
__global__ void __launch_bounds__(128)
q_attn_dwc(const float* __restrict__ dwcw, const float* __restrict__ dwcb)
{
    const int bh = blockIdx.x;
    const int b = bh >> 3, h = bh & 7;
    __shared__ float ag[ANUM_][64];
    __shared__ float av[ANUM_][64];
    __shared__ float ws[64][9];
    __shared__ float wb[64];
    const int tid = threadIdx.x;
    for (int i = tid; i < ANUM_ * 16; i += 128) {
        const int a = i >> 4, c4 = (i & 15) << 2;
        *(float4*)&ag[a][c4] = *(const float4*)&g_agent[((size_t)(b * ANUM_ + a)) * C_ + h * HD_ + c4];
        const float inv = 1.f / g_den[bh * ANUM_ + a];
        float4 n4 = *(const float4*)&g_num[(((size_t)bh * ANUM_) + a) * HD_ + c4];
        n4.x *= inv; n4.y *= inv; n4.z *= inv; n4.w *= inv;
        *(float4*)&av[a][c4] = n4;
    }
    for (int i = tid; i < 64 * 9; i += 128) ws[i / 9][i % 9] = dwcw[(h * 64 + i / 9) * 9 + i % 9];
    if (tid < 64) wb[tid] = dwcb[h * 64 + tid];
    __syncthreads();

    const int n = blockIdx.y * 128 + tid;
    if (n >= N_) return;

    float4 q[16];
    const size_t qb = ((size_t)(b * N_ + n)) * 1536 + h * HD_;
#pragma unroll
    for (int i = 0; i < 16; ++i) q[i] = *(const float4*)&g_qkv[qb + 4 * i];

    float4 o[16];
#pragma unroll
    for (int i = 0; i < 16; ++i) { o[i].x = 0.f; o[i].y = 0.f; o[i].z = 0.f; o[i].w = 0.f; }
    float den = 0.f;

    for (int a = 0; a < ANUM_; ++a) {
        float s = 0.f;
#pragma unroll
        for (int i = 0; i < 16; ++i) {
            const float4 k4 = *(const float4*)&ag[a][4 * i];
            s += q[i].x * k4.x + q[i].y * k4.y + q[i].z * k4.z + q[i].w * k4.w;
        }
        const float w = expf(s * SCALE_F);
        den += w;
#pragma unroll
        for (int i = 0; i < 16; ++i) {
            const float4 v4 = *(const float4*)&av[a][4 * i];
            o[i].x += w * v4.x; o[i].y += w * v4.y; o[i].z += w * v4.z; o[i].w += w * v4.w;
        }
    }

    const float inv = 1.f / den;
#pragma unroll
    for (int i = 0; i < 16; ++i) {
        o[i].x = o[i].x * inv + wb[4 * i + 0];
        o[i].y = o[i].y * inv + wb[4 * i + 1];
        o[i].z = o[i].z * inv + wb[4 * i + 2];
        o[i].w = o[i].w * inv + wb[4 * i + 3];
    }

    const int y = n / H_, x = n - y * H_;
#pragma unroll
    for (int ky = 0; ky < 3; ++ky) {
        const int yy = y + ky - 1;
        if (yy < 0 || yy >= H_) continue;
#pragma unroll
        for (int kx = 0; kx < 3; ++kx) {
            const int xx = x + kx - 1;
            if (xx < 0 || xx >= H_) continue;
            const int tap = ky * 3 + kx;
            const float* vp = &g_qkv[((size_t)(b * N_ + yy * H_ + xx)) * 1536 + 1024 + h * HD_];
#pragma unroll
            for (int i = 0; i < 16; ++i) {
                const float4 v4 = *(const float4*)(vp + 4 * i);
                o[i].x += v4.x * ws[4 * i + 0][tap];
                o[i].y += v4.y * ws[4 * i + 1][tap];
                o[i].z += v4.z * ws[4 * i + 2][tap];
                o[i].w += v4.w * ws[4 * i + 3][tap];
            }
        }
    }

    __half* op = &g_o16[((size_t)(b * N_ + n)) * C_ + h * HD_];
#pragma unroll
    for (int i = 0; i < 16; ++i) {
        __half2 h0 = __floats2half2_rn(o[i].x, o[i].y);
        __half2 h1 = __floats2half2_rn(o[i].z, o[i].w);
        uint2 u;
        u.x = *(uint32_t*)&h0;
        u.y = *(uint32_t*)&h1;
        *(uint2*)(op + 4 * i) = u;
    }
}

// ---------------- launch ----------------
extern "C" void kernel_launch(void* const* d_in, const int* in_sizes, int n_in,
                              void* d_out, int out_size)
{
    const float* x      = (const float*)d_in[0];
    const float* qkv_w  = (const float*)d_in[1];
    const float* proj_w = (const float*)d_in[2];
    const float* proj_b = (const float*)d_in[3];
    const float* dwc_w  = (const float*)d_in[4];
    const float* dwc_b  = (const float*)d_in[5];
    float* out = (float*)d_out;

    float *p_qkv = nullptr;
    __half *p_qkv16 = nullptr, *p_x16 = nullptr, *p_o16 = nullptr, *p_w16 = nullptr;
    cudaGetSymbolAddress((void**)&p_qkv, g_qkv);
    cudaGetSymbolAddress((void**)&p_qkv16, g_qkv16);
    cudaGetSymbolAddress((void**)&p_x16, g_x16);
    cudaGetSymbolAddress((void**)&p_o16, g_o16);
    cudaGetSymbolAddress((void**)&p_w16, g_w16);

    cudaFuncSetAttribute(gemm_h, cudaFuncAttributeMaxDynamicSharedMemorySize, GH_SMEM);
    cudaFuncSetAttribute(agent_kv_mma, cudaFuncAttributeMaxDynamicSharedMemorySize, AK_SMEM);

    // 0. pre-convert inputs to fp16
    cvt_f16<<<(M_ * C_ / 4 + 255) / 256, 256>>>(x, p_x16, M_ * C_ / 4);
    cvt_f16<<<(1536 * 512 / 4 + 255) / 256, 256>>>(qkv_w, p_w16, 1536 * 512 / 4);
    cvt_f16<<<(512 * 512 / 4 + 255) / 256, 256>>>(proj_w, p_w16 + 1536 * 512, 512 * 512 / 4);

    // 1. QKV projection -> g_qkv (fp32) + g_qkv16 (fp16)
    gemm_h<<<dim3(1536 / 128, M_ / 128), 256, GH_SMEM>>>(p_x16, p_w16, p_qkv, p_qkv16, nullptr, 512, 512, 512, 1536);
    // 2. zero agent-attn accumulators
    zero_acc<<<(B_ * NH_ * ANUM_ * HD_ + 255) / 256, 256>>>();
    // 3. agent pooling
    pool_q<<<B_ * ANUM_, C_>>>();
    // 4. agent attention (tensor cores)
    agent_kv_mma<<<dim3(B_ * NH_, 7), 128, AK_SMEM>>>();
    // 5. q attention + fused dwc + fused agent_v normalization -> g_o16 (fp16)
    q_attn_dwc<<<dim3(B_ * NH_, (N_ + 127) / 128), 128>>>(dwc_w, dwc_b);
    // 6. output projection (+bias) -> d_out
    gemm_h<<<dim3(512 / 128, M_ / 128), 256, GH_SMEM>>>(p_o16, p_w16 + 1536 * 512, out, nullptr, proj_b, 512, 512, 512, 512);
}

// round 13
// speedup vs baseline: 2.1519x; 1.3412x over previous
#include <cuda_runtime.h>
#include <cuda_fp16.h>
#include <math.h>
#include <stdint.h>

// ---------------- problem constants ----------------
#define B_    32
#define N_    3136
#define C_    512
#define H_    56
#define NH_   8
#define HD_   64
#define ANUM_ 49
#define SCALE_F 0.125f
#define M_    (B_ * N_)          // 100352

// ---------------- scratch ----------------
__device__ __half g_qkv16[(size_t)M_ * 1536];     // [b,n,{q|k|v},c] fp16
__device__ float  g_agent[B_ * ANUM_ * C_];
__device__ float  g_num[B_ * NH_ * ANUM_ * HD_];
__device__ float  g_den[B_ * NH_ * ANUM_];
__device__ __half g_x16[(size_t)M_ * C_];         // fp16(x)
__device__ __half g_o16[(size_t)M_ * C_];         // fp16 attention(+dwc) out
__device__ __half g_w16[1536 * 512 + 512 * 512];  // fp16 qkv_w | proj_w

// ---------------- helpers ----------------
__device__ __forceinline__ void mma_f16(float* c, const uint32_t* a, const uint32_t* b) {
    asm volatile(
        "mma.sync.aligned.m16n8k16.row.col.f32.f16.f16.f32 "
        "{%0,%1,%2,%3}, {%4,%5,%6,%7}, {%8,%9}, {%0,%1,%2,%3};\n"
        : "+f"(c[0]), "+f"(c[1]), "+f"(c[2]), "+f"(c[3])
        : "r"(a[0]), "r"(a[1]), "r"(a[2]), "r"(a[3]), "r"(b[0]), "r"(b[1]));
}

__device__ __forceinline__ void ldsm4(uint32_t* r, uint32_t addr) {
    asm volatile("ldmatrix.sync.aligned.m8n8.x4.shared.b16 {%0,%1,%2,%3}, [%4];"
                 : "=r"(r[0]), "=r"(r[1]), "=r"(r[2]), "=r"(r[3]) : "r"(addr));
}

__device__ __forceinline__ void ldsm4t(uint32_t* r, uint32_t addr) {
    asm volatile("ldmatrix.sync.aligned.m8n8.x4.trans.shared.b16 {%0,%1,%2,%3}, [%4];"
                 : "=r"(r[0]), "=r"(r[1]), "=r"(r[2]), "=r"(r[3]) : "r"(addr));
}

__device__ __forceinline__ void ldsm2(uint32_t* r, uint32_t addr) {
    asm volatile("ldmatrix.sync.aligned.m8n8.x2.shared.b16 {%0,%1}, [%2];"
                 : "=r"(r[0]), "=r"(r[1]) : "r"(addr));
}

__device__ __forceinline__ uint32_t smem_u32(const void* p) {
    uint32_t a;
    asm("{ .reg .u64 t; cvta.to.shared.u64 t, %1; cvt.u32.u64 %0, t; }" : "=r"(a) : "l"(p));
    return a;
}

__device__ __forceinline__ void cp16(uint32_t dst, const void* src) {
    asm volatile("cp.async.cg.shared.global [%0], [%1], 16;" :: "r"(dst), "l"(src));
}

// ---------------- fp32 -> fp16 pre-convert ----------------
__global__ void cvt_f16(const float* __restrict__ src, __half* __restrict__ dst, int n4)
{
    const int i = blockIdx.x * 256 + threadIdx.x;
    if (i < n4) {
        float4 v = ((const float4*)src)[i];
        __half2 h0 = __floats2half2_rn(v.x, v.y);
        __half2 h1 = __floats2half2_rn(v.z, v.w);
        uint2 u;
        u.x = *(uint32_t*)&h0;
        u.y = *(uint32_t*)&h1;
        ((uint2*)dst)[i] = u;
    }
}

// ---------------- pipelined fp16 tensor-core GEMM --------------------------------
// C[M,N] = A[M,K] * B[N,K]^T (+bias); outputs optional fp32 C and/or fp16 C16.
#define HSTRB  80u
#define GBK    32
#define GSTG   3
#define HSTAGE (128u * HSTRB)
#define GH_SMEM (GSTG * 2 * 10240 + 512)

__global__ void __launch_bounds__(256, 2)
gemm_h(const __half* __restrict__ A, const __half* __restrict__ Bw,
       float* __restrict__ C, __half* __restrict__ C16,
       const float* __restrict__ bias,
       int K, int lda, int ldb, int ldc)
{
    extern __shared__ char smemc[];
    float* bsh = (float*)(smemc + GSTG * 2 * 10240);

    const uint32_t aSmem = smem_u32(smemc);
    const uint32_t bSmem = aSmem + GSTG * HSTAGE;

    const int tid = threadIdx.x;
    const int wid = tid >> 5, lane = tid & 31;
    const int g = lane >> 2, t = lane & 3;
    const int wm = (wid >> 2) * 64;
    const int wn = (wid & 3) * 32;
    const long bm0 = (long)blockIdx.y * 128;
    const long bn0 = (long)blockIdx.x * 128;

    const int lr = tid >> 2;
    const int lj = tid & 3;

    if (tid < 128) bsh[tid] = bias ? bias[bn0 + tid] : 0.f;

    const __half* Ag = A + (bm0 + lr) * (long)lda + lj * 8;
    const __half* Bg = Bw + (bn0 + lr) * (long)ldb + lj * 8;
    const long a64 = 64l * lda, b64 = 64l * ldb;
    const uint32_t soff = (uint32_t)lr * HSTRB + (uint32_t)lj * 16u;

    auto load_stage = [&](int s) {
        const int buf = s % GSTG;
        const __half* Ap = Ag + s * GBK;
        const __half* Bp = Bg + s * GBK;
        const uint32_t bofs = (uint32_t)buf * HSTAGE + soff;
        cp16(aSmem + bofs, Ap);
        cp16(aSmem + bofs + 64u * HSTRB, Ap + a64);
        cp16(bSmem + bofs, Bp);
        cp16(bSmem + bofs + 64u * HSTRB, Bp + b64);
        asm volatile("cp.async.commit_group;" ::: "memory");
    };

    const int aTile = lane >> 3;
    const uint32_t aLane =
        (uint32_t)(((aTile & 1) * 8 + (lane & 7)) * HSTRB + (aTile >> 1) * 16);
    const uint32_t bLane =
        (uint32_t)((lane & 7) * HSTRB + ((lane >> 3) & 1) * 16);

    float acc[4][4][4];
#pragma unroll
    for (int i = 0; i < 4; ++i)
#pragma unroll
        for (int j = 0; j < 4; ++j)
#pragma unroll
            for (int q = 0; q < 4; ++q) acc[i][j][q] = 0.f;

    const int nkt = K / GBK;
    load_stage(0);
    load_stage(1);

    for (int kt = 0; kt < nkt; ++kt) {
        asm volatile("cp.async.wait_group 1;" ::: "memory");
        __syncthreads();
        const uint32_t aCur = aSmem + (uint32_t)(kt % GSTG) * HSTAGE + aLane;
        const uint32_t bCur = bSmem + (uint32_t)(kt % GSTG) * HSTAGE + bLane;

#pragma unroll
        for (int ks = 0; ks < 2; ++ks) {
            uint32_t af[4][4], bf[4][2];
#pragma unroll
            for (int mf = 0; mf < 4; ++mf)
                ldsm4(af[mf], aCur + (uint32_t)(wm + mf * 16) * HSTRB + ks * 32u);
#pragma unroll
            for (int nf = 0; nf < 4; ++nf)
                ldsm2(bf[nf], bCur + (uint32_t)(wn + nf * 8) * HSTRB + ks * 32u);
#pragma unroll
            for (int mf = 0; mf < 4; ++mf)
#pragma unroll
                for (int nf = 0; nf < 4; ++nf)
                    mma_f16(acc[mf][nf], af[mf], bf[nf]);
        }

        if (kt + 2 < nkt) load_stage(kt + 2);
        else asm volatile("cp.async.commit_group;" ::: "memory");
    }

    // epilogue (optional fp32, optional fp16)
#pragma unroll
    for (int mf = 0; mf < 4; ++mf) {
        const long row = bm0 + wm + mf * 16 + g;
#pragma unroll
        for (int nf = 0; nf < 4; ++nf) {
            const int col = wn + nf * 8 + 2 * t;
            float2 v0, v1;
            v0.x = acc[mf][nf][0] + bsh[col];
            v0.y = acc[mf][nf][1] + bsh[col + 1];
            v1.x = acc[mf][nf][2] + bsh[col];
            v1.y = acc[mf][nf][3] + bsh[col + 1];
            if (C) {
                *(float2*)(C + row * (long)ldc + bn0 + col) = v0;
                *(float2*)(C + (row + 8) * (long)ldc + bn0 + col) = v1;
            }
            if (C16) {
                __half2 h0 = __floats2half2_rn(v0.x, v0.y);
                __half2 h1 = __floats2half2_rn(v1.x, v1.y);
                *(uint32_t*)(C16 + row * (long)ldc + bn0 + col) = *(uint32_t*)&h0;
                *(uint32_t*)(C16 + (row + 8) * (long)ldc + bn0 + col) = *(uint32_t*)&h1;
            }
        }
    }
}

// ---------------- agent pooling (fp16 source, fp32 accumulate) ----------------
__global__ void __launch_bounds__(256)
pool_q16()
{
    const int bp = blockIdx.x;
    const int b = bp / ANUM_, p = bp % ANUM_;
    const int ph = p / 7, pw = p % 7;
    const int c2 = threadIdx.x;          // channels 2*c2, 2*c2+1
    float sx = 0.f, sy = 0.f;
#pragma unroll
    for (int iy = 0; iy < 8; ++iy)
#pragma unroll
        for (int ix = 0; ix < 8; ++ix) {
            const int n = (ph * 8 + iy) * H_ + pw * 8 + ix;
            const __half2 v = *(const __half2*)&g_qkv16[((size_t)(b * N_ + n)) * 1536 + 2 * c2];
            const float2 f = __half22float2(v);
            sx += f.x; sy += f.y;
        }
    float2 o;
    o.x = sx * 0.015625f;
    o.y = sy * 0.015625f;
    *(float2*)&g_agent[((size_t)b * ANUM_ + p) * C_ + 2 * c2] = o;
}

__global__ void zero_acc()
{
    const int i = blockIdx.x * 256 + threadIdx.x;
    if (i < B_ * NH_ * ANUM_ * HD_) g_num[i] = 0.f;
    if (i < B_ * NH_ * ANUM_)       g_den[i] = 0.f;
}

// ---------------- agent attention via tensor cores (validated R12) --------------
#define AKROW 144u                    // smem row stride bytes (72 halves)
#define AG_OFF  0u
#define W_OFF   9216u
#define KS_OFF  18432u                // + buf*9216
#define VS_OFF  36864u                // + buf*9216
#define DEN_OFF 55296u
#define AK_SMEM 55552

__global__ void __launch_bounds__(128)
agent_kv_mma()
{
    extern __shared__ char sm[];
    const uint32_t sb = smem_u32(sm);
    float* den_s = (float*)(sm + DEN_OFF);
    __half* ag16 = (__half*)(sm + AG_OFF);
    __half* Wsm  = (__half*)(sm + W_OFF);

    const int bh = blockIdx.x;
    const int part = blockIdx.y;
    const int b = bh >> 3, h = bh & 7;
    const int tid = threadIdx.x;
    const int wid = tid >> 5, lane = tid & 31;
    const int g = lane >> 2, t = lane & 3;
    const int wtok = wid * 16;
    const int wdim = wid * 16;

    for (int i = tid; i < 64 * 64; i += 128) {
        const int a = i >> 6, d = i & 63;
        float v = 0.f;
        if (a < ANUM_)
            v = g_agent[((size_t)(b * ANUM_ + a)) * C_ + h * HD_ + d] * SCALE_F;
        ag16[a * 72 + d] = __float2half(v);
    }
    if (tid < 64) den_s[tid] = 0.f;
    __syncthreads();

    const int aTile = lane >> 3;
    const uint32_t aLane =
        (uint32_t)(((aTile & 1) * 8 + (lane & 7)) * AKROW + (aTile >> 1) * 16);
    const uint32_t bLane =
        (uint32_t)((lane & 7) * AKROW + ((lane >> 3) & 1) * 16);

    uint32_t agF[4][4][4];
#pragma unroll
    for (int mf = 0; mf < 4; ++mf)
#pragma unroll
        for (int ks = 0; ks < 4; ++ks)
            ldsm4(agF[mf][ks], sb + AG_OFF + aLane + (uint32_t)(mf * 16) * AKROW + ks * 32u);

    const int ntok0 = part * 448;
    auto load_tile = [&](int tt) {
        const uint32_t buf = (uint32_t)(tt & 1) * 9216u;
#pragma unroll
        for (int it = 0; it < 4; ++it) {
            const int i = tid + it * 128;
            const int r = i >> 3, cch = i & 7;
            const __half* src =
                g_qkv16 + ((size_t)(b * N_ + ntok0 + tt * 64 + r)) * 1536 + 512 + h * HD_ + cch * 8;
            cp16(sb + KS_OFF + buf + (uint32_t)r * AKROW + cch * 16u, src);
            cp16(sb + VS_OFF + buf + (uint32_t)r * AKROW + cch * 16u, src + 512);
        }
        asm volatile("cp.async.commit_group;" ::: "memory");
    };

    float acc[4][2][4];
#pragma unroll
    for (int i = 0; i < 4; ++i)
#pragma unroll
        for (int j = 0; j < 2; ++j)
#pragma unroll
            for (int q = 0; q < 4; ++q) acc[i][j][q] = 0.f;

    load_tile(0);

    for (int tt = 0; tt < 7; ++tt) {
        asm volatile("cp.async.wait_group 0;" ::: "memory");
        __syncthreads();
        const uint32_t buf = (uint32_t)(tt & 1) * 9216u;

        float c1[4][2][4];
#pragma unroll
        for (int i = 0; i < 4; ++i)
#pragma unroll
            for (int j = 0; j < 2; ++j)
#pragma unroll
                for (int q = 0; q < 4; ++q) c1[i][j][q] = 0.f;

#pragma unroll
        for (int ks = 0; ks < 4; ++ks) {
            uint32_t kF[2][2];
#pragma unroll
            for (int nf = 0; nf < 2; ++nf)
                ldsm2(kF[nf], sb + KS_OFF + buf + bLane +
                      (uint32_t)(wtok + nf * 8) * AKROW + ks * 32u);
#pragma unroll
            for (int mf = 0; mf < 4; ++mf)
#pragma unroll
                for (int nf = 0; nf < 2; ++nf)
                    mma_f16(c1[mf][nf], agF[mf][ks], kF[nf]);
        }

        if (tt + 1 < 7) load_tile(tt + 1);
        else asm volatile("cp.async.commit_group;" ::: "memory");

#pragma unroll
        for (int mf = 0; mf < 4; ++mf) {
            float e[2][4];
#pragma unroll
            for (int nf = 0; nf < 2; ++nf)
#pragma unroll
                for (int q = 0; q < 4; ++q) e[nf][q] = expf(c1[mf][nf][q]);
            float d0 = e[0][0] + e[0][1] + e[1][0] + e[1][1];
            float d1 = e[0][2] + e[0][3] + e[1][2] + e[1][3];
            d0 += __shfl_xor_sync(0xffffffff, d0, 1);
            d0 += __shfl_xor_sync(0xffffffff, d0, 2);
            d1 += __shfl_xor_sync(0xffffffff, d1, 1);
            d1 += __shfl_xor_sync(0xffffffff, d1, 2);
            const int rowA = mf * 16 + g, rowB = rowA + 8;
            if (t == 0) {
                atomicAdd(&den_s[rowA], d0);
                atomicAdd(&den_s[rowB], d1);
            }
#pragma unroll
            for (int nf = 0; nf < 2; ++nf) {
                const int col = wtok + nf * 8 + 2 * t;
                __half2 h0 = __floats2half2_rn(e[nf][0], e[nf][1]);
                __half2 h1 = __floats2half2_rn(e[nf][2], e[nf][3]);
                *(uint32_t*)&Wsm[rowA * 72 + col] = *(uint32_t*)&h0;
                *(uint32_t*)&Wsm[rowB * 72 + col] = *(uint32_t*)&h1;
            }
        }
        __syncthreads();

#pragma unroll
        for (int ks = 0; ks < 4; ++ks) {
            uint32_t vF[4];
            ldsm4t(vF, sb + VS_OFF + buf +
                   (uint32_t)(ks * 16 + (lane & 15)) * AKROW +
                   (uint32_t)(wdim + (lane >> 4) * 8) * 2u);
#pragma unroll
            for (int mf = 0; mf < 4; ++mf) {
                uint32_t wF[4];
                ldsm4(wF, sb + W_OFF + aLane + (uint32_t)(mf * 16) * AKROW + ks * 32u);
                mma_f16(acc[mf][0], wF, vF);
                mma_f16(acc[mf][1], wF, vF + 2);
            }
        }
        __syncthreads();
    }

    if (tid < ANUM_) atomicAdd(&g_den[bh * ANUM_ + tid], den_s[tid]);
#pragma unroll
    for (int mf = 0; mf < 4; ++mf) {
        const int rowA = mf * 16 + g, rowB = rowA + 8;
#pragma unroll
        for (int nf = 0; nf < 2; ++nf) {
            const int dim = wdim + nf * 8 + 2 * t;
            if (rowA < ANUM_) {
                float* p = &g_num[(((size_t)bh * ANUM_) + rowA) * HD_ + dim];
                atomicAdd(p, acc[mf][nf][0]);
                atomicAdd(p + 1, acc[mf][nf][1]);
            }
            if (rowB < ANUM_) {
                float* p = &g_num[(((size_t)bh * ANUM_) + rowB) * HD_ + dim];
                atomicAdd(p, acc[mf][nf][2]);
                atomicAdd(p + 1, acc[mf][nf][3]);
            }
        }
    }
}

// ---------------- q attention via tensor cores ----------------------------------
// Per (bh, part): 7 tiles of 64 tokens.
// phase1: logits[64 tok x 64 agents(pad)] = Q16 @ ag16^T (ag pre-scaled)
// exp -> per-warp den partials -> W fp16 -> phase2: out = W @ av (av^T hoisted)
// den correction: pad agents 49..63 contribute exp(0)=1 each -> subtract 15.
#define QA_AG   0u
#define QA_AV   9216u
#define QA_W    18432u
#define QA_Q    27648u                 // + buf*9216
#define QA_DEN  46080u                 // float[4][64]
#define QA_SMEM 47104

__global__ void __launch_bounds__(128)
q_attn_mma()
{
    extern __shared__ char sm[];
    const uint32_t sb = smem_u32(sm);
    __half* ag16 = (__half*)(sm + QA_AG);
    __half* av16 = (__half*)(sm + QA_AV);
    __half* Wsm  = (__half*)(sm + QA_W);
    float* den_s = (float*)(sm + QA_DEN);

    const int bh = blockIdx.x;
    const int part = blockIdx.y;
    const int b = bh >> 3, h = bh & 7;
    const int tid = threadIdx.x;
    const int wid = tid >> 5, lane = tid & 31;
    const int g = lane >> 2, t = lane & 3;
    const int wagent = wid * 16;         // phase1 col slice
    const int wdim = wid * 16;           // phase2 col slice

    // ag (scaled) and av (normalized agent_v), pad rows 49..63 = 0
    for (int i = tid; i < 64 * 64; i += 128) {
        const int a = i >> 6, d = i & 63;
        float va = 0.f, vv = 0.f;
        if (a < ANUM_) {
            va = g_agent[((size_t)(b * ANUM_ + a)) * C_ + h * HD_ + d] * SCALE_F;
            vv = g_num[(((size_t)bh * ANUM_) + a) * HD_ + d] / g_den[bh * ANUM_ + a];
        }
        ag16[a * 72 + d] = __float2half(va);
        av16[a * 72 + d] = __float2half(vv);
    }
    __syncthreads();

    const int aTile = lane >> 3;
    const uint32_t aLane =
        (uint32_t)(((aTile & 1) * 8 + (lane & 7)) * AKROW + (aTile >> 1) * 16);
    const uint32_t bLane =
        (uint32_t)((lane & 7) * AKROW + ((lane >> 3) & 1) * 16);

    // hoist ag B-frags (phase1) and av^T B-frags (phase2)
    uint32_t agB[4][2][2];
#pragma unroll
    for (int ks = 0; ks < 4; ++ks)
#pragma unroll
        for (int nf = 0; nf < 2; ++nf)
            ldsm2(agB[ks][nf], sb + QA_AG + bLane +
                  (uint32_t)(wagent + nf * 8) * AKROW + ks * 32u);
    uint32_t avB[4][4];
#pragma unroll
    for (int ks = 0; ks < 4; ++ks)
        ldsm4t(avB[ks], sb + QA_AV +
               (uint32_t)(ks * 16 + (lane & 15)) * AKROW +
               (uint32_t)(wdim + (lane >> 4) * 8) * 2u);

    const int ntok0 = part * 448;
    auto load_tile = [&](int tt) {
        const uint32_t buf = (uint32_t)(tt & 1) * 9216u;
#pragma unroll
        for (int it = 0; it < 4; ++it) {
            const int i = tid + it * 128;
            const int r = i >> 3, cch = i & 7;
            const __half* src =
                g_qkv16 + ((size_t)(b * N_ + ntok0 + tt * 64 + r)) * 1536 + h * HD_ + cch * 8;
            cp16(sb + QA_Q + buf + (uint32_t)r * AKROW + cch * 16u, src);
        }
        asm volatile("cp.async.commit_group;" ::: "memory");
    };

    load_tile(0);

    for (int tt = 0; tt < 7; ++tt) {
        asm volatile("cp.async.wait_group 0;" ::: "memory");
        __syncthreads();
        const uint32_t buf = (uint32_t)(tt & 1) * 9216u;

        // phase 1: logits
        float c1[4][2][4];
#pragma unroll
        for (int i = 0; i < 4; ++i)
#pragma unroll
            for (int j = 0; j < 2; ++j)
#pragma unroll
                for (int q = 0; q < 4; ++q) c1[i][j][q] = 0.f;

#pragma unroll
        for (int ks = 0; ks < 4; ++ks) {
            uint32_t qf[4][4];
#pragma unroll
            for (int mf = 0; mf < 4; ++mf)
                ldsm4(qf[mf], sb + QA_Q + buf + aLane +
                      (uint32_t)(mf * 16) * AKROW + ks * 32u);
#pragma unroll
            for (int mf = 0; mf < 4; ++mf)
#pragma unroll
                for (int nf = 0; nf < 2; ++nf)
                    mma_f16(c1[mf][nf], qf[mf], agB[ks][nf]);
        }

        if (tt + 1 < 7) load_tile(tt + 1);
        else asm volatile("cp.async.commit_group;" ::: "memory");

        // exp, per-warp den partials, W store
#pragma unroll
        for (int mf = 0; mf < 4; ++mf) {
            float e[2][4];
#pragma unroll
            for (int nf = 0; nf < 2; ++nf)
#pragma unroll
                for (int q = 0; q < 4; ++q) e[nf][q] = expf(c1[mf][nf][q]);
            float d0 = e[0][0] + e[0][1] + e[1][0] + e[1][1];
            float d1 = e[0][2] + e[0][3] + e[1][2] + e[1][3];
            d0 += __shfl_xor_sync(0xffffffff, d0, 1);
            d0 += __shfl_xor_sync(0xffffffff, d0, 2);
            d1 += __shfl_xor_sync(0xffffffff, d1, 1);
            d1 += __shfl_xor_sync(0xffffffff, d1, 2);
            const int rowA = mf * 16 + g, rowB = rowA + 8;
            if (t == 0) {
                den_s[wid * 64 + rowA] = d0;
                den_s[wid * 64 + rowB] = d1;
            }
#pragma unroll
            for (int nf = 0; nf < 2; ++nf) {
                const int col = wagent + nf * 8 + 2 * t;
                __half2 h0 = __floats2half2_rn(e[nf][0], e[nf][1]);
                __half2 h1 = __floats2half2_rn(e[nf][2], e[nf][3]);
                *(uint32_t*)&Wsm[rowA * 72 + col] = *(uint32_t*)&h0;
                *(uint32_t*)&Wsm[rowB * 72 + col] = *(uint32_t*)&h1;
            }
        }
        __syncthreads();

        // phase 2: out = W @ av
        float acc[4][2][4];
#pragma unroll
        for (int i = 0; i < 4; ++i)
#pragma unroll
            for (int j = 0; j < 2; ++j)
#pragma unroll
                for (int q = 0; q < 4; ++q) acc[i][j][q] = 0.f;

#pragma unroll
        for (int ks = 0; ks < 4; ++ks) {
#pragma unroll
            for (int mf = 0; mf < 4; ++mf) {
                uint32_t wF[4];
                ldsm4(wF, sb + QA_W + aLane + (uint32_t)(mf * 16) * AKROW + ks * 32u);
                mma_f16(acc[mf][0], wF, avB[ks]);
                mma_f16(acc[mf][1], wF, avB[ks] + 2);
            }
        }

        // epilogue: normalize (den - 15 pad correction), write fp16
#pragma unroll
        for (int mf = 0; mf < 4; ++mf) {
            const int rowA = mf * 16 + g, rowB = rowA + 8;
            const float invA = 1.f / (den_s[rowA] + den_s[64 + rowA] +
                                      den_s[128 + rowA] + den_s[192 + rowA] - 15.f);
            const float invB = 1.f / (den_s[rowB] + den_s[64 + rowB] +
                                      den_s[128 + rowB] + den_s[192 + rowB] - 15.f);
            const long tokA = (long)(b * N_ + ntok0 + tt * 64 + rowA);
            const long tokB = (long)(b * N_ + ntok0 + tt * 64 + rowB);
#pragma unroll
            for (int nf = 0; nf < 2; ++nf) {
                const int col = h * HD_ + wdim + nf * 8 + 2 * t;
                __half2 h0 = __floats2half2_rn(acc[mf][nf][0] * invA, acc[mf][nf][1] * invA);
                __half2 h1 = __floats2half2_rn(acc[mf][nf][2] * invB, acc[mf][nf][3] * invB);
                *(uint32_t*)&g_o16[tokA * C_ + col] = *(uint32_t*)&h0;
                *(uint32_t*)&g_o16[tokB * C_ + col] = *(uint32_t*)&h1;
            }
        }
        __syncthreads();
    }
}

// ---------------- depthwise 3x3 conv on v16, += into g_o16 (with bias) ----------
__global__ void __launch_bounds__(256)
dwc16(const float* __restrict__ w, const float* __restrict__ bias)
{
    __shared__ float ws[C_ * 9];
    __shared__ float bs[C_];
    const int b = blockIdx.x, y = blockIdx.y;
    const int tid = threadIdx.x;
    for (int i = tid; i < C_ * 9; i += 256) ws[i] = w[i];
    for (int i = tid; i < C_; i += 256) bs[i] = bias[i];
    __syncthreads();

    for (int i = tid; i < H_ * 64; i += 256) {
        const int x = i >> 6;
        const int c8 = (i & 63) * 8;
        float a[8];
#pragma unroll
        for (int j = 0; j < 8; ++j) a[j] = bs[c8 + j];

#pragma unroll
        for (int ky = 0; ky < 3; ++ky) {
            const int yy = y + ky - 1;
            if (yy < 0 || yy >= H_) continue;
#pragma unroll
            for (int kx = 0; kx < 3; ++kx) {
                const int xx = x + kx - 1;
                if (xx < 0 || xx >= H_) continue;
                const int tap = ky * 3 + kx;
                const uint4 v = *(const uint4*)&g_qkv16[((size_t)(b * N_ + yy * H_ + xx)) * 1536 + 1024 + c8];
                const __half2* vh = (const __half2*)&v;
#pragma unroll
                for (int j2 = 0; j2 < 4; ++j2) {
                    const float2 f = __half22float2(vh[j2]);
                    a[j2 * 2 + 0] += f.x * ws[(c8 + j2 * 2 + 0) * 9 + tap];
                    a[j2 * 2 + 1] += f.y * ws[(c8 + j2 * 2 + 1) * 9 + tap];
                }
            }
        }

        __half* op = &g_o16[((size_t)(b * N_ + y * H_ + x)) * C_ + c8];
        uint4 o = *(uint4*)op;
        __half2* oh = (__half2*)&o;
#pragma unroll
        for (int j2 = 0; j2 < 4; ++j2) {
            float2 f = __half22float2(oh[j2]);
            f.x += a[j2 * 2 + 0];
            f.y += a[j2 * 2 + 1];
            oh[j2] = __floats2half2_rn(f.x, f.y);
        }
        *(uint4*)op = o;
    }
}

// ---------------- launch ----------------
extern "C" void kernel_launch(void* const* d_in, const int* in_sizes, int n_in,
                              void* d_out, int out_size)
{
    const float* x      = (const float*)d_in[0];
    const float* qkv_w  = (const float*)d_in[1];
    const float* proj_w = (const float*)d_in[2];
    const float* proj_b = (const float*)d_in[3];
    const float* dwc_w  = (const float*)d_in[4];
    const float* dwc_b  = (const float*)d_in[5];
    float* out = (float*)d_out;

    __half *p_qkv16 = nullptr, *p_x16 = nullptr, *p_o16 = nullptr, *p_w16 = nullptr;
    cudaGetSymbolAddress((void**)&p_qkv16, g_qkv16);
    cudaGetSymbolAddress((void**)&p_x16, g_x16);
    cudaGetSymbolAddress((void**)&p_o16, g_o16);
    cudaGetSymbolAddress((void**)&p_w16, g_w16);

    cudaFuncSetAttribute(gemm_h, cudaFuncAttributeMaxDynamicSharedMemorySize, GH_SMEM);
    cudaFuncSetAttribute(agent_kv_mma, cudaFuncAttributeMaxDynamicSharedMemorySize, AK_SMEM);
    cudaFuncSetAttribute(q_attn_mma, cudaFuncAttributeMaxDynamicSharedMemorySize, QA_SMEM);

    // 0. pre-convert inputs to fp16
    cvt_f16<<<(M_ * C_ / 4 + 255) / 256, 256>>>(x, p_x16, M_ * C_ / 4);
    cvt_f16<<<(1536 * 512 / 4 + 255) / 256, 256>>>(qkv_w, p_w16, 1536 * 512 / 4);
    cvt_f16<<<(512 * 512 / 4 + 255) / 256, 256>>>(proj_w, p_w16 + 1536 * 512, 512 * 512 / 4);

    // 1. QKV projection -> g_qkv16 (fp16 only)
    gemm_h<<<dim3(1536 / 128, M_ / 128), 256, GH_SMEM>>>(p_x16, p_w16, nullptr, p_qkv16, nullptr, 512, 512, 512, 1536);
    // 2. zero agent-attn accumulators
    zero_acc<<<(B_ * NH_ * ANUM_ * HD_ + 255) / 256, 256>>>();
    // 3. agent pooling (fp16 source)
    pool_q16<<<B_ * ANUM_, 256>>>();
    // 4. agent attention (tensor cores)
    agent_kv_mma<<<dim3(B_ * NH_, 7), 128, AK_SMEM>>>();
    // 5. q attention (tensor cores) -> g_o16
    q_attn_mma<<<dim3(B_ * NH_, 7), 128, QA_SMEM>>>();
    // 6. depthwise conv on v16, += into g_o16 (with bias)
    dwc16<<<dim3(B_, H_), 256>>>(dwc_w, dwc_b);
    // 7. output projection (+bias) -> d_out (fp32)
    gemm_h<<<dim3(512 / 128, M_ / 128), 256, GH_SMEM>>>(p_o16, p_w16 + 1536 * 512, out, nullptr, proj_b, 512, 512, 512, 512);
}